// round 5
// baseline (speedup 1.0000x reference)
#include <cuda_runtime.h>
#include <math.h>

#define SS 128
#define BB 32
#define VV 32000
#define NINP 1024
#define NHID 1024
#define NHEADS 16
#define HD 64
#define KSPLIT 8

// ---------------- device scratch (packed bf16 word = {lo16=elem0, hi16=elem1}) --------
static __device__ unsigned g_wq_h[1024 * 1024], g_wq_l[1024 * 1024];          // q_w  [1024][2048]
static __device__ unsigned g_wi_h[4096 * 2048], g_wi_l[4096 * 2048];          // int_w permuted [4096][4096]
static __device__ unsigned g_wf_h[3072 * 2048], g_wf_l[3072 * 2048];          // fin_w [3072][4096]
static __device__ unsigned g_wd_h[32000 * 512], g_wd_l[32000 * 512];          // dec_w [32000][1024]
static __device__ unsigned g_eh[(size_t)SS * BB * 512], g_el[(size_t)SS * BB * 512];
static __device__ unsigned g_xh[BB * 1536], g_xl[BB * 1536];                  // [hidden|q|attn]
static __device__ unsigned g_ih[BB * 2048], g_il[BB * 2048];                  // inter
static __device__ unsigned g_sh[4096 * 512], g_sl[4096 * 512];                // decoder A (states)
static __device__ float g_q[BB * 1024];                                       // fp32 q for attn
static __device__ float g_kcache[(size_t)(SS + 1) * BB * NHID];
static __device__ float g_vcache[(size_t)(SS + 1) * BB * NHID];
static __device__ float g_part[KSPLIT * BB * 4096];

// ---------------- helpers ----------------
__device__ __forceinline__ unsigned packbf(float e, float o) {
    unsigned r;
    asm("cvt.rn.bf16x2.f32 %0, %1, %2;" : "=r"(r) : "f"(o), "f"(e));
    return r;
}
__device__ __forceinline__ void splitpair(float v0, float v1, unsigned& h, unsigned& l) {
    h = packbf(v0, v1);
    float r0 = v0 - __uint_as_float(h << 16);
    float r1 = v1 - __uint_as_float(h & 0xffff0000u);
    l = packbf(r0, r1);
}
__device__ __forceinline__ void mmabf(float* c, unsigned a0, unsigned a1, unsigned a2,
                                      unsigned a3, unsigned b0, unsigned b1) {
    asm volatile(
        "mma.sync.aligned.m16n8k16.row.col.f32.bf16.bf16.f32 "
        "{%0,%1,%2,%3},{%4,%5,%6,%7},{%8,%9},{%0,%1,%2,%3};"
        : "+f"(c[0]), "+f"(c[1]), "+f"(c[2]), "+f"(c[3])
        : "r"(a0), "r"(a1), "r"(a2), "r"(a3), "r"(b0), "r"(b1));
}

// ---------------- one-time conversion: fp32 [rows][2*Kw] -> packed bf16 hi/lo words ------
__global__ void k_cvt(const float* __restrict__ src, unsigned* __restrict__ dh,
                      unsigned* __restrict__ dl, int sh, long total, int permute) {
    long stride = (long)gridDim.x * blockDim.x;
    for (long i = (long)blockIdx.x * blockDim.x + threadIdx.x; i < total; i += stride) {
        long row = i >> sh;
        int w = (int)(i & ((1 << sh) - 1));
        int k = 2 * w;
        int kk = k;
        if (permute) kk = (k < 1024) ? k : ((k < 2048) ? k + 2048 : k - 1024);
        float2 v = *(const float2*)(src + (row << (sh + 1)) + kk);
        unsigned h, l;
        splitpair(v.x, v.y, h, l);
        dh[i] = h;
        dl[i] = l;
    }
}

// ---------------- setup ----------------
__global__ void k_init(const float* __restrict__ h0, const float* __restrict__ kc0,
                       const float* __restrict__ vc0, float* __restrict__ states_full) {
    int b = blockIdx.x, t = threadIdx.x;
    float4 h = ((const float4*)(h0 + b * NHID))[t];
    unsigned w0, l0, w1, l1;
    splitpair(h.x, h.y, w0, l0);
    splitpair(h.z, h.w, w1, l1);
    g_xh[b * 1536 + 2 * t] = w0;     g_xl[b * 1536 + 2 * t] = l0;
    g_xh[b * 1536 + 2 * t + 1] = w1; g_xl[b * 1536 + 2 * t + 1] = l1;
    ((float4*)(states_full + (size_t)b * NHID))[t] = h;
    ((float4*)(g_kcache + (size_t)b * NHID))[t] = ((const float4*)(kc0 + b * NHID))[t];
    ((float4*)(g_vcache + (size_t)b * NHID))[t] = ((const float4*)(vc0 + b * NHID))[t];
}

__global__ void k_embed(const int* __restrict__ obs, const float* __restrict__ enc_w) {
    int idx = blockIdx.x;  // s*B + b
    int row = obs[idx];
    int t = threadIdx.x;
    float4 v = ((const float4*)(enc_w + (size_t)row * NINP))[t];
    unsigned h0, l0, h1, l1;
    splitpair(v.x, v.y, h0, l0);
    splitpair(v.z, v.w, h1, l1);
    size_t o = (size_t)idx * 512 + 2 * t;
    g_eh[o] = h0; g_el[o] = l0;
    g_eh[o + 1] = h1; g_el[o + 1] = l1;
}

// ---------------- step GEMM: part[b,n] = sum_k x[b,k]*W[n,k]; M=32, N-tile 64, splitK=8 ---
// operands are packed bf16 words; 3-term bf16x3. Kw/klenw in words (2 elems each).
__global__ __launch_bounds__(256) void k_gemm(int estep, int xsel,
                                              const unsigned* __restrict__ Wh,
                                              const unsigned* __restrict__ Wl,
                                              int Kw, int klenw, int N) {
    __shared__ unsigned xh[32][36], xl[32][36], wh[64][36], wl[64][36];
    const int tid = threadIdx.x;
    const int nb = blockIdx.x * 64;
    const int k0 = blockIdx.y * klenw;
    const int w = tid >> 5, lane = tid & 31, g = lane >> 2, tig = lane & 3;

    const unsigned* eh = g_eh + (size_t)(estep > 0 ? estep : 0) * BB * 512;
    const unsigned* el = g_el + (size_t)(estep > 0 ? estep : 0) * BB * 512;

    float acc[2][4] = {};
    uint4 xa[2], wa[4];

    const int xr = tid >> 3, xg = (tid & 7) << 2;   // x: 32 rows x 8 uint4-groups
    auto loadx = [&](int kcw) {
        int wc = kcw + xg;
        const unsigned *sh_, *sl_;
        if (xsel == 0) {
            if (wc < 512) { sh_ = eh + xr * 512 + wc; sl_ = el + xr * 512 + wc; }
            else { sh_ = g_xh + xr * 1536 + wc - 512; sl_ = g_xl + xr * 1536 + wc - 512; }
        } else {
            sh_ = g_ih + xr * 2048 + wc; sl_ = g_il + xr * 2048 + wc;
        }
        xa[0] = *(const uint4*)sh_;
        xa[1] = *(const uint4*)sl_;
#pragma unroll
        for (int i = 0; i < 2; i++) {
            int e = tid + i * 256;
            int rr = e >> 3, gg = (e & 7) << 2;
            size_t off = (size_t)(nb + rr) * Kw + kcw + gg;
            wa[i] = *(const uint4*)(Wh + off);
            wa[2 + i] = *(const uint4*)(Wl + off);
        }
    };
    auto store = [&]() {
        *(uint4*)&xh[xr][xg] = xa[0];
        *(uint4*)&xl[xr][xg] = xa[1];
#pragma unroll
        for (int i = 0; i < 2; i++) {
            int e = tid + i * 256;
            int rr = e >> 3, gg = (e & 7) << 2;
            *(uint4*)&wh[rr][gg] = wa[i];
            *(uint4*)&wl[rr][gg] = wa[2 + i];
        }
    };

    const int nchunks = klenw >> 5;
    loadx(k0);
    for (int c = 0; c < nchunks; c++) {
        store();
        __syncthreads();
        if (c + 1 < nchunks) loadx(k0 + (c + 1) * 32);
#pragma unroll
        for (int s = 0; s < 4; s++) {
            int w0 = s * 8 + tig, w1 = w0 + 4;
            unsigned bh0 = wh[w * 8 + g][w0], bh1 = wh[w * 8 + g][w1];
            unsigned bl0 = wl[w * 8 + g][w0], bl1 = wl[w * 8 + g][w1];
#pragma unroll
            for (int mt = 0; mt < 2; mt++) {
                int r0 = mt * 16 + g;
                unsigned ah0 = xh[r0][w0], ah1 = xh[r0 + 8][w0];
                unsigned ah2 = xh[r0][w1], ah3 = xh[r0 + 8][w1];
                unsigned al0 = xl[r0][w0], al1 = xl[r0 + 8][w0];
                unsigned al2 = xl[r0][w1], al3 = xl[r0 + 8][w1];
                mmabf(acc[mt], ah0, ah1, ah2, ah3, bh0, bh1);
                mmabf(acc[mt], ah0, ah1, ah2, ah3, bl0, bl1);
                mmabf(acc[mt], al0, al1, al2, al3, bh0, bh1);
            }
        }
        __syncthreads();
    }
    float* p = g_part + (size_t)blockIdx.y * 32 * N;
    int n0 = nb + w * 8 + 2 * tig;
#pragma unroll
    for (int mt = 0; mt < 2; mt++) {
        int r0 = mt * 16 + g;
        *(float2*)&p[r0 * N + n0] = make_float2(acc[mt][0], acc[mt][1]);
        *(float2*)&p[(r0 + 8) * N + n0] = make_float2(acc[mt][2], acc[mt][3]);
    }
}

// ---------------- fused LN(q)+relu + attention; 32 blocks x 512 threads (warp = head) ----
__global__ __launch_bounds__(512) void k_lnq_attn(const float* __restrict__ qb,
                                                  const float* __restrict__ gg,
                                                  const float* __restrict__ bbv, int step) {
    __shared__ float q[1024];
    __shared__ float sc[NHEADS][132];
    __shared__ float r1[16], r2[16];
    int b = blockIdx.x, tid = threadIdx.x, lane = tid & 31, wid = tid >> 5;

    // LN over 1024 cols; thread owns cols 2t, 2t+1
    float2 v = *(const float2*)(qb + 2 * tid);
#pragma unroll
    for (int j = 0; j < KSPLIT; j++) {
        float2 p = *(const float2*)(g_part + (size_t)j * 32 * 1024 + b * 1024 + 2 * tid);
        v.x += p.x; v.y += p.y;
    }
    float s1 = v.x + v.y, s2 = v.x * v.x + v.y * v.y;
#pragma unroll
    for (int o = 16; o; o >>= 1) {
        s1 += __shfl_xor_sync(0xffffffffu, s1, o);
        s2 += __shfl_xor_sync(0xffffffffu, s2, o);
    }
    if (lane == 0) { r1[wid] = s1; r2[wid] = s2; }
    __syncthreads();
    s1 = 0.f; s2 = 0.f;
#pragma unroll
    for (int i = 0; i < 16; i++) { s1 += r1[i]; s2 += r2[i]; }
    float mu = s1 * (1.f / 1024.f);
    float rstd = rsqrtf(s2 * (1.f / 1024.f) - mu * mu + 1e-5f);
    float q0 = fmaxf((v.x - mu) * rstd * gg[2 * tid] + bbv[2 * tid], 0.f);
    float q1 = fmaxf((v.y - mu) * rstd * gg[2 * tid + 1] + bbv[2 * tid + 1], 0.f);
    q[2 * tid] = q0;
    q[2 * tid + 1] = q1;
    unsigned h_, l_;
    splitpair(q0, q1, h_, l_);
    g_xh[b * 1536 + 512 + tid] = h_;
    g_xl[b * 1536 + 512 + tid] = l_;
    g_q[b * 1024 + 2 * tid] = q0;       // kept for debug/verif symmetry
    g_q[b * 1024 + 2 * tid + 1] = q1;
    __syncthreads();

    // attention: warp wid handles head wid
    int hh = wid;
    int L = step + 1;
    const float* qh = q + hh * HD;
    float msc[4], m = -1e30f;
#pragma unroll
    for (int i = 0; i < 4; i++) {
        int c = lane + i * 32;
        float d = -1e30f;
        if (c < L) {
            const float* kr = g_kcache + ((size_t)c * BB + b) * NHID + hh * HD;
            float acc = 0.f;
#pragma unroll
            for (int j = 0; j < 16; j++) {
                float4 kv = *(const float4*)&kr[j * 4];
                acc += qh[j * 4] * kv.x + qh[j * 4 + 1] * kv.y +
                       qh[j * 4 + 2] * kv.z + qh[j * 4 + 3] * kv.w;
            }
            d = acc * 0.125f;
        }
        msc[i] = d;
        m = fmaxf(m, d);
    }
#pragma unroll
    for (int o = 16; o; o >>= 1) m = fmaxf(m, __shfl_xor_sync(0xffffffffu, m, o));
    float se = 0.f;
#pragma unroll
    for (int i = 0; i < 4; i++) {
        float e = expf(msc[i] - m);   // c >= L -> exp(-huge) = 0
        sc[hh][lane + i * 32] = e;
        se += e;
    }
#pragma unroll
    for (int o = 16; o; o >>= 1) se += __shfl_xor_sync(0xffffffffu, se, o);
    float inv = 1.f / se;
    __syncwarp();

    // weighted V sum: lane owns dims 2*lane, 2*lane+1
    float o0 = 0.f, o1 = 0.f;
    const float* vbase = g_vcache + (size_t)b * NHID + hh * HD + 2 * lane;
    for (int c = 0; c < L; c++) {
        float wgt = sc[hh][c];
        float2 vv = *(const float2*)(vbase + (size_t)c * BB * NHID);
        o0 += wgt * vv.x;
        o1 += wgt * vv.y;
    }
    o0 *= inv; o1 *= inv;
    unsigned oh, ol;
    splitpair(o0, o1, oh, ol);
    g_xh[b * 1536 + 1024 + hh * 32 + lane] = oh;
    g_xl[b * 1536 + 1024 + hh * 32 + lane] = ol;
}

// ---------------- LN(int)+relu -> packed inter ----------------
__global__ __launch_bounds__(256) void k_ln_int(const float* __restrict__ bias,
                                                const float* __restrict__ gg,
                                                const float* __restrict__ bb2) {
    __shared__ float r1[8], r2[8];
    int b = blockIdx.x, tid = threadIdx.x, lane = tid & 31, wid = tid >> 5;
    float pre[16];
    float s1 = 0.f, s2 = 0.f;
#pragma unroll
    for (int i = 0; i < 8; i++) {
        int c = 2 * (tid + i * 256);
        float2 v = *(const float2*)&bias[c];
#pragma unroll
        for (int j = 0; j < KSPLIT; j++) {
            float2 p = *(const float2*)&g_part[(size_t)j * 32 * 4096 + b * 4096 + c];
            v.x += p.x; v.y += p.y;
        }
        pre[2 * i] = v.x; pre[2 * i + 1] = v.y;
        s1 += v.x + v.y;
        s2 += v.x * v.x + v.y * v.y;
    }
#pragma unroll
    for (int o = 16; o; o >>= 1) {
        s1 += __shfl_xor_sync(0xffffffffu, s1, o);
        s2 += __shfl_xor_sync(0xffffffffu, s2, o);
    }
    if (lane == 0) { r1[wid] = s1; r2[wid] = s2; }
    __syncthreads();
    s1 = 0.f; s2 = 0.f;
#pragma unroll
    for (int i = 0; i < 8; i++) { s1 += r1[i]; s2 += r2[i]; }
    float mu = s1 * (1.f / 4096.f);
    float rstd = rsqrtf(s2 * (1.f / 4096.f) - mu * mu + 1e-5f);
#pragma unroll
    for (int i = 0; i < 8; i++) {
        int wd = tid + i * 256, c = 2 * wd;
        float y0 = fmaxf((pre[2 * i] - mu) * rstd * gg[c] + bb2[c], 0.f);
        float y1 = fmaxf((pre[2 * i + 1] - mu) * rstd * gg[c + 1] + bb2[c + 1], 0.f);
        unsigned h_, l_;
        splitpair(y0, y1, h_, l_);
        g_ih[b * 2048 + wd] = h_;
        g_il[b * 2048 + wd] = l_;
    }
}

// ---------------- LN(fin)+relu -> kcache, vcache, states(+decoder A), hidden ------------
__global__ __launch_bounds__(256) void k_ln_fin(const float* __restrict__ bias,
                                                const float* __restrict__ gg,
                                                const float* __restrict__ bb2, int step,
                                                float* __restrict__ states_full) {
    __shared__ float r1[8], r2[8];
    int b = blockIdx.x, tid = threadIdx.x, lane = tid & 31, wid = tid >> 5;
    float pre[12];
    float s1 = 0.f, s2 = 0.f;
#pragma unroll
    for (int i = 0; i < 6; i++) {
        int c = 2 * (tid + i * 256);
        float2 v = *(const float2*)&bias[c];
#pragma unroll
        for (int j = 0; j < KSPLIT; j++) {
            float2 p = *(const float2*)&g_part[(size_t)j * 32 * 3072 + b * 3072 + c];
            v.x += p.x; v.y += p.y;
        }
        pre[2 * i] = v.x; pre[2 * i + 1] = v.y;
        s1 += v.x + v.y;
        s2 += v.x * v.x + v.y * v.y;
    }
#pragma unroll
    for (int o = 16; o; o >>= 1) {
        s1 += __shfl_xor_sync(0xffffffffu, s1, o);
        s2 += __shfl_xor_sync(0xffffffffu, s2, o);
    }
    if (lane == 0) { r1[wid] = s1; r2[wid] = s2; }
    __syncthreads();
    s1 = 0.f; s2 = 0.f;
#pragma unroll
    for (int i = 0; i < 8; i++) { s1 += r1[i]; s2 += r2[i]; }
    float mu = s1 * (1.f / 3072.f);
    float rstd = rsqrtf(s2 * (1.f / 3072.f) - mu * mu + 1e-5f);
#pragma unroll
    for (int i = 0; i < 6; i++) {
        int wd = tid + i * 256, c = 2 * wd;
        float y0 = fmaxf((pre[2 * i] - mu) * rstd * gg[c] + bb2[c], 0.f);
        float y1 = fmaxf((pre[2 * i + 1] - mu) * rstd * gg[c + 1] + bb2[c + 1], 0.f);
        if (c < 1024) {
            *(float2*)&g_kcache[((size_t)(step + 1) * BB + b) * NHID + c] = make_float2(y0, y1);
        } else if (c < 2048) {
            *(float2*)&g_vcache[((size_t)(step + 1) * BB + b) * NHID + (c - 1024)] =
                make_float2(y0, y1);
        } else {
            int d = c - 2048;
            *(float2*)&states_full[((size_t)(step + 1) * BB + b) * NHID + d] = make_float2(y0, y1);
            unsigned h_, l_;
            splitpair(y0, y1, h_, l_);
            g_xh[b * 1536 + (wd - 1024)] = h_;
            g_xl[b * 1536 + (wd - 1024)] = l_;
            g_sh[((size_t)step * 32 + b) * 512 + (wd - 1024)] = h_;
            g_sl[((size_t)step * 32 + b) * 512 + (wd - 1024)] = l_;
        }
    }
}

// ---------------- decoder GEMM: logits = states @ dec_w.T + dec_b ------------------------
__global__ __launch_bounds__(256, 1) void k_dec(const float* __restrict__ bias,
                                                float* __restrict__ out) {
    __shared__ unsigned ah[128][20], al[128][20], bh_[128][20], bl_[128][20];
    int tid = threadIdx.x;
    int mb = blockIdx.x * 128, nb = blockIdx.y * 128;
    int w = tid >> 5, lane = tid & 31, g = lane >> 2, tig = lane & 3;
    int mw = w >> 2, nw = w & 3;
    float acc[4][4][4] = {};
    uint4 ra[4], rw[4];

    auto load = [&](int kcw) {
#pragma unroll
        for (int i = 0; i < 2; i++) {
            int e = tid + i * 256;
            int r = e >> 2, g4 = (e & 3) << 2;
            size_t oa = (size_t)(mb + r) * 512 + kcw + g4;
            size_t ow = (size_t)(nb + r) * 512 + kcw + g4;
            ra[i] = *(const uint4*)(g_sh + oa);
            ra[2 + i] = *(const uint4*)(g_sl + oa);
            rw[i] = *(const uint4*)(g_wd_h + ow);
            rw[2 + i] = *(const uint4*)(g_wd_l + ow);
        }
    };
    auto store = [&]() {
#pragma unroll
        for (int i = 0; i < 2; i++) {
            int e = tid + i * 256;
            int r = e >> 2, g4 = (e & 3) << 2;
            *(uint4*)&ah[r][g4] = ra[i];
            *(uint4*)&al[r][g4] = ra[2 + i];
            *(uint4*)&bh_[r][g4] = rw[i];
            *(uint4*)&bl_[r][g4] = rw[2 + i];
        }
    };

    load(0);
    for (int c = 0; c < 32; c++) {
        store();
        __syncthreads();
        if (c < 31) load((c + 1) * 16);
#pragma unroll
        for (int s = 0; s < 2; s++) {
            int w0 = s * 8 + tig, w1 = w0 + 4;
            unsigned bh[4][2], bl[4][2];
#pragma unroll
            for (int nt = 0; nt < 4; nt++) {
                int col = nw * 32 + nt * 8 + g;
                bh[nt][0] = bh_[col][w0]; bh[nt][1] = bh_[col][w1];
                bl[nt][0] = bl_[col][w0]; bl[nt][1] = bl_[col][w1];
            }
#pragma unroll
            for (int mt = 0; mt < 4; mt++) {
                int r0 = mw * 64 + mt * 16 + g;
                unsigned a0 = ah[r0][w0], a1 = ah[r0 + 8][w0], a2 = ah[r0][w1], a3 = ah[r0 + 8][w1];
                unsigned l0 = al[r0][w0], l1 = al[r0 + 8][w0], l2 = al[r0][w1], l3 = al[r0 + 8][w1];
#pragma unroll
                for (int nt = 0; nt < 4; nt++) {
                    mmabf(acc[mt][nt], a0, a1, a2, a3, bh[nt][0], bh[nt][1]);
                    mmabf(acc[mt][nt], a0, a1, a2, a3, bl[nt][0], bl[nt][1]);
                    mmabf(acc[mt][nt], l0, l1, l2, l3, bh[nt][0], bh[nt][1]);
                }
            }
        }
        __syncthreads();
    }
#pragma unroll
    for (int mt = 0; mt < 4; mt++) {
        int r0 = mb + mw * 64 + mt * 16 + g;
#pragma unroll
        for (int nt = 0; nt < 4; nt++) {
            int c0 = nb + nw * 32 + nt * 8 + 2 * tig;
            float2 bv = *(const float2*)&bias[c0];
            *(float2*)&out[(size_t)r0 * VV + c0] =
                make_float2(acc[mt][nt][0] + bv.x, acc[mt][nt][1] + bv.y);
            *(float2*)&out[(size_t)(r0 + 8) * VV + c0] =
                make_float2(acc[mt][nt][2] + bv.x, acc[mt][nt][3] + bv.y);
        }
    }
}

// ---------------- launch ----------------
extern "C" void kernel_launch(void* const* d_in, const int* in_sizes, int n_in,
                              void* d_out, int out_size) {
    (void)in_sizes; (void)n_in; (void)out_size;
    const int* obs = (const int*)d_in[0];
    const float* hidden_init = (const float*)d_in[1];
    const float* kinit = (const float*)d_in[2];
    const float* vinit = (const float*)d_in[3];
    const float* enc_w = (const float*)d_in[4];
    const float* q_w = (const float*)d_in[5];
    const float* q_b = (const float*)d_in[6];
    const float* qn_g = (const float*)d_in[7];
    const float* qn_b = (const float*)d_in[8];
    const float* int_w = (const float*)d_in[9];
    const float* int_b = (const float*)d_in[10];
    const float* intn_g = (const float*)d_in[11];
    const float* intn_b = (const float*)d_in[12];
    const float* fin_w = (const float*)d_in[13];
    const float* fin_b = (const float*)d_in[14];
    const float* fn_g = (const float*)d_in[15];
    const float* fn_b = (const float*)d_in[16];
    const float* dec_w = (const float*)d_in[17];
    const float* dec_b = (const float*)d_in[18];

    float* logits = (float*)d_out;
    float* states_full = logits + (size_t)SS * BB * VV;

    unsigned *wq_h, *wq_l, *wi_h, *wi_l, *wf_h, *wf_l, *wd_h, *wd_l;
    cudaGetSymbolAddress((void**)&wq_h, g_wq_h);
    cudaGetSymbolAddress((void**)&wq_l, g_wq_l);
    cudaGetSymbolAddress((void**)&wi_h, g_wi_h);
    cudaGetSymbolAddress((void**)&wi_l, g_wi_l);
    cudaGetSymbolAddress((void**)&wf_h, g_wf_h);
    cudaGetSymbolAddress((void**)&wf_l, g_wf_l);
    cudaGetSymbolAddress((void**)&wd_h, g_wd_h);
    cudaGetSymbolAddress((void**)&wd_l, g_wd_l);

    // one-time operand conversion (runs inside the graph, amortized vs 128 reuses)
    k_cvt<<<2048, 256>>>(q_w, wq_h, wq_l, 10, (long)1024 * 1024, 0);
    k_cvt<<<2048, 256>>>(int_w, wi_h, wi_l, 11, (long)4096 * 2048, 1);
    k_cvt<<<2048, 256>>>(fin_w, wf_h, wf_l, 11, (long)3072 * 2048, 0);
    k_cvt<<<2048, 256>>>(dec_w, wd_h, wd_l, 9, (long)32000 * 512, 0);
    k_embed<<<SS * BB, 256>>>(obs, enc_w);
    k_init<<<BB, 256>>>(hidden_init, kinit, vinit, states_full);

    for (int s = 0; s < SS; s++) {
        k_gemm<<<dim3(16, KSPLIT), 256>>>(s, 0, wq_h, wq_l, 1024, 1024 / KSPLIT, 1024);
        k_lnq_attn<<<BB, 512>>>(q_b, qn_g, qn_b, s);
        k_gemm<<<dim3(64, KSPLIT), 256>>>(s, 0, wi_h, wi_l, 2048, 2048 / KSPLIT, 4096);
        k_ln_int<<<BB, 256>>>(int_b, intn_g, intn_b);
        k_gemm<<<dim3(48, KSPLIT), 256>>>(-1, 1, wf_h, wf_l, 2048, 2048 / KSPLIT, 3072);
        k_ln_fin<<<BB, 256>>>(fin_b, fn_g, fn_b, s, states_full);
    }

    k_dec<<<dim3(32, VV / 128), 256>>>(dec_b, logits);
}

// round 6
// speedup vs baseline: 1.0395x; 1.0395x over previous
#include <cuda_runtime.h>
#include <math.h>

#define SS 128
#define BB 32
#define VV 32000
#define NINP 1024
#define NHID 1024
#define NHEADS 16
#define HD 64
#define KSPLIT 8

// ---------------- device scratch (no runtime allocs allowed) ----------------
static __device__ float g_emb[(size_t)SS * BB * NINP];       // raw fp32 embeddings
static __device__ float g_xbuf[BB * 3072];                   // [hidden|q|attn] fp32
static __device__ float g_kcache[(size_t)(SS + 1) * BB * NHID];
static __device__ float g_vcache[(size_t)(SS + 1) * BB * NHID];
static __device__ float g_inter[BB * 4096];
static __device__ float g_part[KSPLIT * BB * 4096];          // split-K partials

// ---------------- helpers ----------------
__device__ __forceinline__ unsigned packbf(float e, float o) {
    // word = {lo16 = bf16(e), hi16 = bf16(o)}
    unsigned r;
    asm("cvt.rn.bf16x2.f32 %0, %1, %2;" : "=r"(r) : "f"(o), "f"(e));
    return r;
}

// fp32x4 (4 consecutive k) -> 2 hi words + 2 lo words (bf16 pair split)
__device__ __forceinline__ void cvtpair(float4 v, unsigned* ph, unsigned* pl) {
    unsigned h0 = packbf(v.x, v.y);
    unsigned h1 = packbf(v.z, v.w);
    float r0 = v.x - __uint_as_float(h0 << 16);
    float r1 = v.y - __uint_as_float(h0 & 0xffff0000u);
    float r2 = v.z - __uint_as_float(h1 << 16);
    float r3 = v.w - __uint_as_float(h1 & 0xffff0000u);
    ph[0] = h0; ph[1] = h1;
    pl[0] = packbf(r0, r1);
    pl[1] = packbf(r2, r3);
}

__device__ __forceinline__ void mmabf(float* c, unsigned a0, unsigned a1, unsigned a2,
                                      unsigned a3, unsigned b0, unsigned b1) {
    asm volatile(
        "mma.sync.aligned.m16n8k16.row.col.f32.bf16.bf16.f32 "
        "{%0,%1,%2,%3},{%4,%5,%6,%7},{%8,%9},{%0,%1,%2,%3};"
        : "+f"(c[0]), "+f"(c[1]), "+f"(c[2]), "+f"(c[3])
        : "r"(a0), "r"(a1), "r"(a2), "r"(a3), "r"(b0), "r"(b1));
}

// ---------------- setup ----------------
__global__ void k_init(const float* __restrict__ h0, const float* __restrict__ kc0,
                       const float* __restrict__ vc0, float* __restrict__ states_full) {
    int b = blockIdx.x, t = threadIdx.x;
    float4 h = ((const float4*)(h0 + b * NHID))[t];
    ((float4*)(g_xbuf + b * 3072))[t] = h;
    ((float4*)(states_full + (size_t)b * NHID))[t] = h;
    ((float4*)(g_kcache + (size_t)b * NHID))[t] = ((const float4*)(kc0 + b * NHID))[t];
    ((float4*)(g_vcache + (size_t)b * NHID))[t] = ((const float4*)(vc0 + b * NHID))[t];
}

__global__ void k_embed(const int* __restrict__ obs, const float* __restrict__ enc_w) {
    int idx = blockIdx.x;  // s*B + b
    int row = obs[idx];
    ((float4*)(g_emb + (size_t)idx * NINP))[threadIdx.x] =
        ((const float4*)(enc_w + (size_t)row * NINP))[threadIdx.x];
}

// ---------------- step GEMM: part[b,n] = sum_k x[b,k]*W[n,k], M=32, N-tile=64, splitK=8 ----
// fp32 loads, bf16-pair split in staging, double-buffered smem (one barrier per chunk).
__global__ __launch_bounds__(256) void k_gemm_step(int estep, int xsel,
                                                   const float* __restrict__ W,
                                                   int K, int klen, int N, int permute) {
    extern __shared__ unsigned dsm[];
    unsigned* XH = dsm;                    // [2][32][36]
    unsigned* XL = XH + 2 * 32 * 36;       // [2][32][36]
    unsigned* WH = XL + 2 * 32 * 36;       // [2][64][36]
    unsigned* WL = WH + 2 * 64 * 36;       // [2][64][36]

    const int tid = threadIdx.x;
    const int nb = blockIdx.x * 64;
    const int k0 = blockIdx.y * klen;
    const int w = tid >> 5, lane = tid & 31, g = lane >> 2, tig = lane & 3;

    const float* xe = g_emb + (size_t)(estep > 0 ? estep : 0) * BB * NINP;
    const int ecols = (estep >= 0) ? NINP : 0;
    const float* xr = xsel ? g_inter : g_xbuf;
    const int xstride = xsel ? 4096 : 3072;

    float acc[2][4] = {};
    float4 xa[2], wa[4];

    auto loadx = [&](int kc) {
#pragma unroll
        for (int i = 0; i < 2; i++) {
            int e = tid + i * 256;
            int r = e >> 4, cg = (e & 15) << 2;
            int gc = kc + cg;
            const float* src = (gc < ecols) ? (xe + r * NINP + gc)
                                            : (xr + r * xstride + (gc - ecols));
            xa[i] = *(const float4*)src;
        }
#pragma unroll
        for (int i = 0; i < 4; i++) {
            int e = tid + i * 256;
            int r = e >> 4, cg = (e & 15) << 2;
            int gc = kc + cg;
            int wc = gc;
            if (permute) wc = (gc < 1024) ? gc : ((gc < 2048) ? gc + 2048 : gc - 1024);
            wa[i] = *(const float4*)(W + (size_t)(nb + r) * K + wc);
        }
    };
    auto store = [&](int bf) {
        unsigned* xh = XH + bf * 1152;
        unsigned* xl = XL + bf * 1152;
        unsigned* wh = WH + bf * 2304;
        unsigned* wl = WL + bf * 2304;
#pragma unroll
        for (int i = 0; i < 2; i++) {
            int e = tid + i * 256;
            int r = e >> 4, wd = (e & 15) * 2;
            cvtpair(xa[i], &xh[r * 36 + wd], &xl[r * 36 + wd]);
        }
#pragma unroll
        for (int i = 0; i < 4; i++) {
            int e = tid + i * 256;
            int r = e >> 4, wd = (e & 15) * 2;
            cvtpair(wa[i], &wh[r * 36 + wd], &wl[r * 36 + wd]);
        }
    };

    const int nchunks = klen >> 6;
    loadx(k0);
    store(0);
    __syncthreads();
    for (int c = 0; c < nchunks; c++) {
        const int cur = c & 1;
        unsigned* xh = XH + cur * 1152;
        unsigned* xl = XL + cur * 1152;
        unsigned* wh = WH + cur * 2304;
        unsigned* wl = WL + cur * 2304;
        if (c + 1 < nchunks) loadx(k0 + (c + 1) * 64);
#pragma unroll
        for (int s = 0; s < 4; s++) {
            int w0 = s * 8 + tig, w1 = w0 + 4;
            unsigned bh0 = wh[(w * 8 + g) * 36 + w0], bh1 = wh[(w * 8 + g) * 36 + w1];
            unsigned bl0 = wl[(w * 8 + g) * 36 + w0], bl1 = wl[(w * 8 + g) * 36 + w1];
#pragma unroll
            for (int mt = 0; mt < 2; mt++) {
                int r0 = mt * 16 + g;
                unsigned ah0 = xh[r0 * 36 + w0], ah1 = xh[(r0 + 8) * 36 + w0];
                unsigned ah2 = xh[r0 * 36 + w1], ah3 = xh[(r0 + 8) * 36 + w1];
                unsigned al0 = xl[r0 * 36 + w0], al1 = xl[(r0 + 8) * 36 + w0];
                unsigned al2 = xl[r0 * 36 + w1], al3 = xl[(r0 + 8) * 36 + w1];
                mmabf(acc[mt], ah0, ah1, ah2, ah3, bh0, bh1);
                mmabf(acc[mt], ah0, ah1, ah2, ah3, bl0, bl1);
                mmabf(acc[mt], al0, al1, al2, al3, bh0, bh1);
            }
        }
        if (c + 1 < nchunks) store((c + 1) & 1);
        __syncthreads();
    }
    float* p = g_part + (size_t)blockIdx.y * 32 * N;
    int n0 = nb + w * 8 + 2 * tig;
#pragma unroll
    for (int mt = 0; mt < 2; mt++) {
        int r0 = mt * 16 + g;
        *(float2*)&p[r0 * N + n0] = make_float2(acc[mt][0], acc[mt][1]);
        *(float2*)&p[(r0 + 8) * N + n0] = make_float2(acc[mt][2], acc[mt][3]);
    }
}

// ---------------- fused LN(q)+relu + attention; 32 blocks x 512 threads (warp = head) ----
__global__ __launch_bounds__(512) void k_lnq_attn(const float* __restrict__ qb,
                                                  const float* __restrict__ gg,
                                                  const float* __restrict__ bbv, int step) {
    __shared__ float q[1024];
    __shared__ float sc[NHEADS][132];
    __shared__ float r1[16], r2[16];
    int b = blockIdx.x, tid = threadIdx.x, lane = tid & 31, wid = tid >> 5;

    // LN over 1024 cols; thread owns cols 2t, 2t+1
    float2 v = *(const float2*)(qb + 2 * tid);
#pragma unroll
    for (int j = 0; j < KSPLIT; j++) {
        float2 p = *(const float2*)(g_part + (size_t)j * 32 * 1024 + b * 1024 + 2 * tid);
        v.x += p.x; v.y += p.y;
    }
    float s1 = v.x + v.y, s2 = v.x * v.x + v.y * v.y;
#pragma unroll
    for (int o = 16; o; o >>= 1) {
        s1 += __shfl_xor_sync(0xffffffffu, s1, o);
        s2 += __shfl_xor_sync(0xffffffffu, s2, o);
    }
    if (lane == 0) { r1[wid] = s1; r2[wid] = s2; }
    __syncthreads();
    s1 = 0.f; s2 = 0.f;
#pragma unroll
    for (int i = 0; i < 16; i++) { s1 += r1[i]; s2 += r2[i]; }
    float mu = s1 * (1.f / 1024.f);
    float rstd = rsqrtf(s2 * (1.f / 1024.f) - mu * mu + 1e-5f);
    float q0 = fmaxf((v.x - mu) * rstd * gg[2 * tid] + bbv[2 * tid], 0.f);
    float q1 = fmaxf((v.y - mu) * rstd * gg[2 * tid + 1] + bbv[2 * tid + 1], 0.f);
    q[2 * tid] = q0;
    q[2 * tid + 1] = q1;
    *(float2*)&g_xbuf[b * 3072 + 1024 + 2 * tid] = make_float2(q0, q1);
    __syncthreads();

    // attention: warp wid handles head wid
    const int hh = wid;
    const int L = step + 1;
    const float* qh = q + hh * HD;
    float msc[4], m = -1e30f;
#pragma unroll
    for (int i = 0; i < 4; i++) {
        int c = lane + i * 32;
        float d = -1e30f;
        if (c < L) {
            const float* kr = g_kcache + ((size_t)c * BB + b) * NHID + hh * HD;
            float acc = 0.f;
#pragma unroll
            for (int j = 0; j < 16; j++) {
                float4 kv = *(const float4*)&kr[j * 4];
                acc += qh[j * 4] * kv.x + qh[j * 4 + 1] * kv.y +
                       qh[j * 4 + 2] * kv.z + qh[j * 4 + 3] * kv.w;
            }
            d = acc * 0.125f;
        }
        msc[i] = d;
        m = fmaxf(m, d);
    }
#pragma unroll
    for (int o = 16; o; o >>= 1) m = fmaxf(m, __shfl_xor_sync(0xffffffffu, m, o));
    float se = 0.f;
#pragma unroll
    for (int i = 0; i < 4; i++) {
        float e = expf(msc[i] - m);   // c >= L -> exp(-huge) = 0
        sc[hh][lane + i * 32] = e;
        se += e;
    }
#pragma unroll
    for (int o = 16; o; o >>= 1) se += __shfl_xor_sync(0xffffffffu, se, o);
    float inv = 1.f / se;
    __syncwarp();

    // weighted V sum: lane owns dims 2*lane, 2*lane+1
    float o0 = 0.f, o1 = 0.f;
    const float* vbase = g_vcache + (size_t)b * NHID + hh * HD + 2 * lane;
#pragma unroll 4
    for (int c = 0; c < L; c++) {
        float wgt = sc[hh][c];
        float2 vv = *(const float2*)(vbase + (size_t)c * BB * NHID);
        o0 += wgt * vv.x;
        o1 += wgt * vv.y;
    }
    *(float2*)&g_xbuf[b * 3072 + 2048 + hh * HD + 2 * lane] = make_float2(o0 * inv, o1 * inv);
}

// ---------------- LN(int)+relu -> g_inter ----------------
__global__ __launch_bounds__(256) void k_ln_int(const float* __restrict__ bias,
                                                const float* __restrict__ gg,
                                                const float* __restrict__ bb2) {
    __shared__ float pre[4096];
    __shared__ float red1[8], red2[8];
    int b = blockIdx.x, tid = threadIdx.x, lane = tid & 31, wid = tid >> 5;
    float s1 = 0.f, s2 = 0.f;
#pragma unroll
    for (int i = 0; i < 4; i++) {
        int c = (tid + i * 256) * 4;
        float4 v = *(const float4*)&bias[c];
#pragma unroll
        for (int j = 0; j < KSPLIT; j++) {
            float4 p = *(const float4*)&g_part[(size_t)j * 32 * 4096 + b * 4096 + c];
            v.x += p.x; v.y += p.y; v.z += p.z; v.w += p.w;
        }
        *(float4*)&pre[c] = v;
        s1 += v.x + v.y + v.z + v.w;
        s2 += v.x * v.x + v.y * v.y + v.z * v.z + v.w * v.w;
    }
#pragma unroll
    for (int o = 16; o; o >>= 1) {
        s1 += __shfl_xor_sync(0xffffffffu, s1, o);
        s2 += __shfl_xor_sync(0xffffffffu, s2, o);
    }
    if (lane == 0) { red1[wid] = s1; red2[wid] = s2; }
    __syncthreads();
    s1 = 0.f; s2 = 0.f;
#pragma unroll
    for (int i = 0; i < 8; i++) { s1 += red1[i]; s2 += red2[i]; }
    float mu = s1 * (1.f / 4096.f);
    float rstd = rsqrtf(s2 * (1.f / 4096.f) - mu * mu + 1e-5f);
#pragma unroll
    for (int i = 0; i < 16; i++) {
        int c = tid + i * 256;
        g_inter[b * 4096 + c] = fmaxf((pre[c] - mu) * rstd * gg[c] + bb2[c], 0.f);
    }
}

// ---------------- LN(fin)+relu -> kcache[i+1], vcache[i+1], hidden/states ----------------
__global__ __launch_bounds__(256) void k_ln_fin(const float* __restrict__ bias,
                                                const float* __restrict__ gg,
                                                const float* __restrict__ bb2, int step,
                                                float* __restrict__ states_full) {
    __shared__ float pre[3072];
    __shared__ float red1[8], red2[8];
    int b = blockIdx.x, tid = threadIdx.x, lane = tid & 31, wid = tid >> 5;
    float s1 = 0.f, s2 = 0.f;
#pragma unroll
    for (int i = 0; i < 3; i++) {
        int c = (tid + i * 256) * 4;
        float4 v = *(const float4*)&bias[c];
#pragma unroll
        for (int j = 0; j < KSPLIT; j++) {
            float4 p = *(const float4*)&g_part[(size_t)j * 32 * 3072 + b * 3072 + c];
            v.x += p.x; v.y += p.y; v.z += p.z; v.w += p.w;
        }
        *(float4*)&pre[c] = v;
        s1 += v.x + v.y + v.z + v.w;
        s2 += v.x * v.x + v.y * v.y + v.z * v.z + v.w * v.w;
    }
#pragma unroll
    for (int o = 16; o; o >>= 1) {
        s1 += __shfl_xor_sync(0xffffffffu, s1, o);
        s2 += __shfl_xor_sync(0xffffffffu, s2, o);
    }
    if (lane == 0) { red1[wid] = s1; red2[wid] = s2; }
    __syncthreads();
    s1 = 0.f; s2 = 0.f;
#pragma unroll
    for (int i = 0; i < 8; i++) { s1 += red1[i]; s2 += red2[i]; }
    float mu = s1 * (1.f / 3072.f);
    float rstd = rsqrtf(s2 * (1.f / 3072.f) - mu * mu + 1e-5f);
#pragma unroll
    for (int i = 0; i < 12; i++) {
        int c = tid + i * 256;
        float y = fmaxf((pre[c] - mu) * rstd * gg[c] + bb2[c], 0.f);
        if (c < 1024) {
            g_kcache[((size_t)(step + 1) * BB + b) * NHID + c] = y;
        } else if (c < 2048) {
            g_vcache[((size_t)(step + 1) * BB + b) * NHID + (c - 1024)] = y;
        } else {
            int d = c - 2048;
            states_full[((size_t)(step + 1) * BB + b) * NHID + d] = y;
            g_xbuf[b * 3072 + d] = y;
        }
    }
}

// ---------------- decoder GEMM: logits[r,n] = states[r,:]@dec_w[n,:] + dec_b[n] ------------
// 128x128 tile, bf16-pair 3-term, double-buffered smem, m-fastest grid for dec_w L2 reuse
__global__ __launch_bounds__(256, 1) void k_dec(const float* __restrict__ A,
                                                const float* __restrict__ Wd,
                                                const float* __restrict__ bias,
                                                float* __restrict__ out) {
    extern __shared__ unsigned dsm[];
    unsigned* AH = dsm;                  // [2][128][20]
    unsigned* AL = AH + 2 * 128 * 20;
    unsigned* BH = AL + 2 * 128 * 20;
    unsigned* BL = BH + 2 * 128 * 20;

    int tid = threadIdx.x;
    int mb = blockIdx.x * 128, nb = blockIdx.y * 128;
    int w = tid >> 5, lane = tid & 31, g = lane >> 2, tig = lane & 3;
    int mw = w >> 2, nw = w & 3;  // 2 m-warps x 4 n-warps
    float acc[4][4][4] = {};
    float4 aa[4], wv[4];

    auto load = [&](int kc) {
#pragma unroll
        for (int i = 0; i < 4; i++) {
            int e = tid + i * 256;
            int r = e >> 3, cg = (e & 7) << 2;
            aa[i] = *(const float4*)(A + (size_t)(mb + r) * 1024 + kc + cg);
            wv[i] = *(const float4*)(Wd + (size_t)(nb + r) * 1024 + kc + cg);
        }
    };
    auto store = [&](int bf) {
        unsigned* ah = AH + bf * 2560;
        unsigned* al = AL + bf * 2560;
        unsigned* bh = BH + bf * 2560;
        unsigned* bl = BL + bf * 2560;
#pragma unroll
        for (int i = 0; i < 4; i++) {
            int e = tid + i * 256;
            int r = e >> 3, wd = (e & 7) * 2;
            cvtpair(aa[i], &ah[r * 20 + wd], &al[r * 20 + wd]);
            cvtpair(wv[i], &bh[r * 20 + wd], &bl[r * 20 + wd]);
        }
    };

    load(0);
    store(0);
    __syncthreads();
    for (int c = 0; c < 32; c++) {
        const int cur = c & 1;
        unsigned* ah = AH + cur * 2560;
        unsigned* al = AL + cur * 2560;
        unsigned* bh_ = BH + cur * 2560;
        unsigned* bl_ = BL + cur * 2560;
        if (c < 31) load((c + 1) * 32);
#pragma unroll
        for (int s = 0; s < 2; s++) {
            int w0 = s * 8 + tig, w1 = w0 + 4;
            unsigned bh[4][2], bl[4][2];
#pragma unroll
            for (int nt = 0; nt < 4; nt++) {
                int col = nw * 32 + nt * 8 + g;
                bh[nt][0] = bh_[col * 20 + w0]; bh[nt][1] = bh_[col * 20 + w1];
                bl[nt][0] = bl_[col * 20 + w0]; bl[nt][1] = bl_[col * 20 + w1];
            }
#pragma unroll
            for (int mt = 0; mt < 4; mt++) {
                int r0 = mw * 64 + mt * 16 + g;
                unsigned a0 = ah[r0 * 20 + w0], a1 = ah[(r0 + 8) * 20 + w0];
                unsigned a2 = ah[r0 * 20 + w1], a3 = ah[(r0 + 8) * 20 + w1];
                unsigned l0 = al[r0 * 20 + w0], l1 = al[(r0 + 8) * 20 + w0];
                unsigned l2 = al[r0 * 20 + w1], l3 = al[(r0 + 8) * 20 + w1];
#pragma unroll
                for (int nt = 0; nt < 4; nt++) {
                    mmabf(acc[mt][nt], a0, a1, a2, a3, bh[nt][0], bh[nt][1]);
                    mmabf(acc[mt][nt], a0, a1, a2, a3, bl[nt][0], bl[nt][1]);
                    mmabf(acc[mt][nt], l0, l1, l2, l3, bh[nt][0], bh[nt][1]);
                }
            }
        }
        if (c < 31) store((c + 1) & 1);
        __syncthreads();
    }
#pragma unroll
    for (int mt = 0; mt < 4; mt++) {
        int r0 = mb + mw * 64 + mt * 16 + g;
#pragma unroll
        for (int nt = 0; nt < 4; nt++) {
            int c0 = nb + nw * 32 + nt * 8 + 2 * tig;
            float2 bv = *(const float2*)&bias[c0];
            *(float2*)&out[(size_t)r0 * VV + c0] =
                make_float2(acc[mt][nt][0] + bv.x, acc[mt][nt][1] + bv.y);
            *(float2*)&out[(size_t)(r0 + 8) * VV + c0] =
                make_float2(acc[mt][nt][2] + bv.x, acc[mt][nt][3] + bv.y);
        }
    }
}

// ---------------- launch ----------------
extern "C" void kernel_launch(void* const* d_in, const int* in_sizes, int n_in,
                              void* d_out, int out_size) {
    (void)in_sizes; (void)n_in; (void)out_size;
    const int* obs = (const int*)d_in[0];
    const float* hidden_init = (const float*)d_in[1];
    const float* kinit = (const float*)d_in[2];
    const float* vinit = (const float*)d_in[3];
    const float* enc_w = (const float*)d_in[4];
    const float* q_w = (const float*)d_in[5];
    const float* q_b = (const float*)d_in[6];
    const float* qn_g = (const float*)d_in[7];
    const float* qn_b = (const float*)d_in[8];
    const float* int_w = (const float*)d_in[9];
    const float* int_b = (const float*)d_in[10];
    const float* intn_g = (const float*)d_in[11];
    const float* intn_b = (const float*)d_in[12];
    const float* fin_w = (const float*)d_in[13];
    const float* fin_b = (const float*)d_in[14];
    const float* fn_g = (const float*)d_in[15];
    const float* fn_b = (const float*)d_in[16];
    const float* dec_w = (const float*)d_in[17];
    const float* dec_b = (const float*)d_in[18];

    float* logits = (float*)d_out;
    float* states_full = logits + (size_t)SS * BB * VV;

    const int GEMM_SMEM = (2 * 1152 * 2 + 2 * 2304 * 2) * 4;  // 55296 B
    const int DEC_SMEM = 4 * 2 * 128 * 20 * 4;                // 81920 B
    cudaFuncSetAttribute(k_gemm_step, cudaFuncAttributeMaxDynamicSharedMemorySize, GEMM_SMEM);
    cudaFuncSetAttribute(k_dec, cudaFuncAttributeMaxDynamicSharedMemorySize, DEC_SMEM);

    k_init<<<BB, 256>>>(hidden_init, kinit, vinit, states_full);
    k_embed<<<SS * BB, 256>>>(obs, enc_w);

    for (int s = 0; s < SS; s++) {
        // q = relu(ln([e,hidden] @ q_w.T + q_b))
        k_gemm_step<<<dim3(16, KSPLIT), 256, GEMM_SMEM>>>(s, 0, q_w, 2048, 2048 / KSPLIT, 1024, 0);
        k_lnq_attn<<<BB, 512>>>(q_b, qn_g, qn_b, s);
        // inter = relu(ln([e,q,attn,hidden] @ int_w.T + int_b)); x order [e,hidden,q,attn]
        k_gemm_step<<<dim3(64, KSPLIT), 256, GEMM_SMEM>>>(s, 0, int_w, 4096, 4096 / KSPLIT, 4096, 1);
        k_ln_int<<<BB, 256>>>(int_b, intn_g, intn_b);
        // final = relu(ln(inter @ fin_w.T + fin_b)) -> split k,v,h
        k_gemm_step<<<dim3(48, KSPLIT), 256, GEMM_SMEM>>>(-1, 1, fin_w, 4096, 4096 / KSPLIT, 3072, 0);
        k_ln_fin<<<BB, 256>>>(fin_b, fn_g, fn_b, s, states_full);
    }

    // logits = states @ dec_w.T + dec_b  (states = states_full rows 1..S)
    k_dec<<<dim3(32, VV / 128), 256, DEC_SMEM>>>(states_full + BB * NHID, dec_w, dec_b, logits);
}

// round 7
// speedup vs baseline: 1.0656x; 1.0251x over previous
#include <cuda_runtime.h>
#include <math.h>

#define SS 128
#define BB 32
#define VV 32000
#define NINP 1024
#define NHID 1024
#define NHEADS 16
#define HD 64
#define KSPLIT 8

// ---------------- device scratch (no runtime allocs allowed) ----------------
static __device__ float g_emb[(size_t)SS * BB * NINP];       // raw fp32 embeddings
static __device__ float g_xbuf[BB * 3072];                   // [hidden|q|attn] fp32
static __device__ float g_kcache[(size_t)(SS + 1) * BB * NHID];
static __device__ float g_vcache[(size_t)(SS + 1) * BB * NHID];
static __device__ float g_inter[BB * 4096];
static __device__ float g_part[KSPLIT * BB * 4096];          // split-K partials
static __device__ unsigned g_cnt[2];                         // arrival counters (int, fin)

// ---------------- helpers ----------------
__device__ __forceinline__ unsigned packbf(float e, float o) {
    // word = {lo16 = bf16(e), hi16 = bf16(o)}
    unsigned r;
    asm("cvt.rn.bf16x2.f32 %0, %1, %2;" : "=r"(r) : "f"(o), "f"(e));
    return r;
}

// fp32x4 (4 consecutive k) -> 2 hi words + 2 lo words (bf16 pair split)
__device__ __forceinline__ void cvtpair(float4 v, unsigned* ph, unsigned* pl) {
    unsigned h0 = packbf(v.x, v.y);
    unsigned h1 = packbf(v.z, v.w);
    float r0 = v.x - __uint_as_float(h0 << 16);
    float r1 = v.y - __uint_as_float(h0 & 0xffff0000u);
    float r2 = v.z - __uint_as_float(h1 << 16);
    float r3 = v.w - __uint_as_float(h1 & 0xffff0000u);
    ph[0] = h0; ph[1] = h1;
    pl[0] = packbf(r0, r1);
    pl[1] = packbf(r2, r3);
}

__device__ __forceinline__ void mmabf(float* c, unsigned a0, unsigned a1, unsigned a2,
                                      unsigned a3, unsigned b0, unsigned b1) {
    asm volatile(
        "mma.sync.aligned.m16n8k16.row.col.f32.bf16.bf16.f32 "
        "{%0,%1,%2,%3},{%4,%5,%6,%7},{%8,%9},{%0,%1,%2,%3};"
        : "+f"(c[0]), "+f"(c[1]), "+f"(c[2]), "+f"(c[3])
        : "r"(a0), "r"(a1), "r"(a2), "r"(a3), "r"(b0), "r"(b1));
}

// ---------------- setup ----------------
__global__ void k_init(const float* __restrict__ h0, const float* __restrict__ kc0,
                       const float* __restrict__ vc0, float* __restrict__ states_full) {
    int b = blockIdx.x, t = threadIdx.x;
    if (b == 0 && t == 0) { g_cnt[0] = 0; g_cnt[1] = 0; }
    float4 h = ((const float4*)(h0 + b * NHID))[t];
    ((float4*)(g_xbuf + b * 3072))[t] = h;
    ((float4*)(states_full + (size_t)b * NHID))[t] = h;
    ((float4*)(g_kcache + (size_t)b * NHID))[t] = ((const float4*)(kc0 + b * NHID))[t];
    ((float4*)(g_vcache + (size_t)b * NHID))[t] = ((const float4*)(vc0 + b * NHID))[t];
}

__global__ void k_embed(const int* __restrict__ obs, const float* __restrict__ enc_w) {
    int idx = blockIdx.x;  // s*B + b
    int row = obs[idx];
    ((float4*)(g_emb + (size_t)idx * NINP))[threadIdx.x] =
        ((const float4*)(enc_w + (size_t)row * NINP))[threadIdx.x];
}

// ---------------- step GEMM (round-4 mainloop, verbatim schedule) ----------------
// part[b,n] = sum_k x[b,k]*W[n,k]; M=32, N-tile=64, splitK=8.
// lnmode: 0 = none; 1 = LN(int) epilogue -> g_inter; 2 = LN(fin) epilogue -> caches/states.
// Epilogue: ticket on g_cnt[lnmode-1]; last 32 tickets each LN one batch row.
__global__ __launch_bounds__(256) void k_gemm_step(int estep, int xsel,
                                                   const float* __restrict__ W,
                                                   int K, int klen, int N, int permute,
                                                   int lnmode, int step,
                                                   const float* __restrict__ lnb,
                                                   const float* __restrict__ lng,
                                                   const float* __restrict__ lnbeta,
                                                   float* __restrict__ states_full) {
    __shared__ unsigned sm[6912];        // xh[32][36] | xl[32][36] | wh[64][36] | wl[64][36]
    unsigned (*xh)[36] = (unsigned(*)[36])sm;
    unsigned (*xl)[36] = (unsigned(*)[36])(sm + 1152);
    unsigned (*wh)[36] = (unsigned(*)[36])(sm + 2304);
    unsigned (*wl)[36] = (unsigned(*)[36])(sm + 4608);

    const int tid = threadIdx.x;
    const int nb = blockIdx.x * 64;
    const int k0 = blockIdx.y * klen;
    const int w = tid >> 5, lane = tid & 31, g = lane >> 2, tig = lane & 3;

    const float* xe = g_emb + (size_t)(estep > 0 ? estep : 0) * BB * NINP;
    const int ecols = (estep >= 0) ? NINP : 0;
    const float* xr = xsel ? g_inter : g_xbuf;
    const int xstride = xsel ? 4096 : 3072;

    float acc[2][4] = {};
    float4 xa[2], wa[4];

    auto loadx = [&](int kc) {
#pragma unroll
        for (int i = 0; i < 2; i++) {
            int e = tid + i * 256;
            int r = e >> 4, cg = (e & 15) << 2;
            int gc = kc + cg;
            const float* src = (gc < ecols) ? (xe + r * NINP + gc)
                                            : (xr + r * xstride + (gc - ecols));
            xa[i] = *(const float4*)src;
        }
#pragma unroll
        for (int i = 0; i < 4; i++) {
            int e = tid + i * 256;
            int r = e >> 4, cg = (e & 15) << 2;
            int gc = kc + cg;
            int wc = gc;
            if (permute) wc = (gc < 1024) ? gc : ((gc < 2048) ? gc + 2048 : gc - 1024);
            wa[i] = *(const float4*)(W + (size_t)(nb + r) * K + wc);
        }
    };
    auto store = [&]() {
#pragma unroll
        for (int i = 0; i < 2; i++) {
            int e = tid + i * 256;
            int r = e >> 4, wd = (e & 15) * 2;
            cvtpair(xa[i], &xh[r][wd], &xl[r][wd]);
        }
#pragma unroll
        for (int i = 0; i < 4; i++) {
            int e = tid + i * 256;
            int r = e >> 4, wd = (e & 15) * 2;
            cvtpair(wa[i], &wh[r][wd], &wl[r][wd]);
        }
    };

    const int nchunks = klen >> 6;
    loadx(k0);
    for (int c = 0; c < nchunks; c++) {
        store();
        __syncthreads();
        if (c + 1 < nchunks) loadx(k0 + (c + 1) * 64);
#pragma unroll
        for (int s = 0; s < 4; s++) {
            int w0 = s * 8 + tig, w1 = w0 + 4;
            unsigned bh0 = wh[w * 8 + g][w0], bh1 = wh[w * 8 + g][w1];
            unsigned bl0 = wl[w * 8 + g][w0], bl1 = wl[w * 8 + g][w1];
#pragma unroll
            for (int mt = 0; mt < 2; mt++) {
                int r0 = mt * 16 + g;
                unsigned ah0 = xh[r0][w0], ah1 = xh[r0 + 8][w0];
                unsigned ah2 = xh[r0][w1], ah3 = xh[r0 + 8][w1];
                unsigned al0 = xl[r0][w0], al1 = xl[r0 + 8][w0];
                unsigned al2 = xl[r0][w1], al3 = xl[r0 + 8][w1];
                mmabf(acc[mt], ah0, ah1, ah2, ah3, bh0, bh1);
                mmabf(acc[mt], ah0, ah1, ah2, ah3, bl0, bl1);
                mmabf(acc[mt], al0, al1, al2, al3, bh0, bh1);
            }
        }
        __syncthreads();
    }
    float* p = g_part + (size_t)blockIdx.y * 32 * N;
    int n0 = nb + w * 8 + 2 * tig;
#pragma unroll
    for (int mt = 0; mt < 2; mt++) {
        int r0 = mt * 16 + g;
        *(float2*)&p[r0 * N + n0] = make_float2(acc[mt][0], acc[mt][1]);
        *(float2*)&p[(r0 + 8) * N + n0] = make_float2(acc[mt][2], acc[mt][3]);
    }

    if (lnmode == 0) return;

    // -------- fused LN epilogue via arrival ticket --------
    __threadfence();
    __shared__ unsigned tkt;
    if (tid == 0) tkt = atomicAdd(&g_cnt[lnmode - 1], 1u) + 1u;
    __syncthreads();
    const unsigned nbt = gridDim.x * gridDim.y;
    const unsigned base = (unsigned)step * nbt;
    const unsigned t = tkt;
    if (t <= base + nbt - 32u) return;
    const int row = (int)(t - (base + nbt - 32u) - 1u);   // 0..31

    if (tid == 0) {
        while (atomicAdd(&g_cnt[lnmode - 1], 0u) < base + nbt) { }
        __threadfence();
    }
    __syncthreads();
    __threadfence();

    // LN over N cols of batch row `row`; reuse block smem
    float* pre = (float*)sm;                 // up to 4096 floats = 16 KB (smem is 27.6 KB)
    float* red1 = (float*)(sm + 4200);
    float* red2 = red1 + 8;
    const int iters = N >> 10;               // N/1024: 4 (int) or 3 (fin)
    float s1 = 0.f, s2 = 0.f;
    for (int i = 0; i < iters; i++) {
        int c = (tid + i * 256) * 4;
        float4 v = *(const float4*)&lnb[c];
#pragma unroll
        for (int j = 0; j < KSPLIT; j++) {
            float4 q = *(const float4*)&g_part[(size_t)j * 32 * N + row * N + c];
            v.x += q.x; v.y += q.y; v.z += q.z; v.w += q.w;
        }
        *(float4*)&pre[c] = v;
        s1 += v.x + v.y + v.z + v.w;
        s2 += v.x * v.x + v.y * v.y + v.z * v.z + v.w * v.w;
    }
#pragma unroll
    for (int o = 16; o; o >>= 1) {
        s1 += __shfl_xor_sync(0xffffffffu, s1, o);
        s2 += __shfl_xor_sync(0xffffffffu, s2, o);
    }
    if (lane == 0) { red1[w] = s1; red2[w] = s2; }
    __syncthreads();
    s1 = 0.f; s2 = 0.f;
#pragma unroll
    for (int i = 0; i < 8; i++) { s1 += red1[i]; s2 += red2[i]; }
    const float invN = 1.f / (float)N;
    float mu = s1 * invN;
    float rstd = rsqrtf(s2 * invN - mu * mu + 1e-5f);

    if (lnmode == 1) {
        for (int i = 0; i < 16; i++) {
            int c = tid + i * 256;
            g_inter[row * 4096 + c] = fmaxf((pre[c] - mu) * rstd * lng[c] + lnbeta[c], 0.f);
        }
    } else {
        for (int i = 0; i < 12; i++) {
            int c = tid + i * 256;
            float y = fmaxf((pre[c] - mu) * rstd * lng[c] + lnbeta[c], 0.f);
            if (c < 1024) {
                g_kcache[((size_t)(step + 1) * BB + row) * NHID + c] = y;
            } else if (c < 2048) {
                g_vcache[((size_t)(step + 1) * BB + row) * NHID + (c - 1024)] = y;
            } else {
                int d = c - 2048;
                states_full[((size_t)(step + 1) * BB + row) * NHID + d] = y;
                g_xbuf[row * 3072 + d] = y;
            }
        }
    }
}

// ---------------- fused LN(q)+relu + attention; 32 blocks x 512 threads (warp = head) ----
__global__ __launch_bounds__(512) void k_lnq_attn(const float* __restrict__ qb,
                                                  const float* __restrict__ gg,
                                                  const float* __restrict__ bbv, int step) {
    __shared__ float q[1024];
    __shared__ float sc[NHEADS][132];
    __shared__ float r1[16], r2[16];
    int b = blockIdx.x, tid = threadIdx.x, lane = tid & 31, wid = tid >> 5;

    // LN over 1024 cols; thread owns cols 2t, 2t+1
    float2 v = *(const float2*)(qb + 2 * tid);
#pragma unroll
    for (int j = 0; j < KSPLIT; j++) {
        float2 p = *(const float2*)(g_part + (size_t)j * 32 * 1024 + b * 1024 + 2 * tid);
        v.x += p.x; v.y += p.y;
    }
    float s1 = v.x + v.y, s2 = v.x * v.x + v.y * v.y;
#pragma unroll
    for (int o = 16; o; o >>= 1) {
        s1 += __shfl_xor_sync(0xffffffffu, s1, o);
        s2 += __shfl_xor_sync(0xffffffffu, s2, o);
    }
    if (lane == 0) { r1[wid] = s1; r2[wid] = s2; }
    __syncthreads();
    s1 = 0.f; s2 = 0.f;
#pragma unroll
    for (int i = 0; i < 16; i++) { s1 += r1[i]; s2 += r2[i]; }
    float mu = s1 * (1.f / 1024.f);
    float rstd = rsqrtf(s2 * (1.f / 1024.f) - mu * mu + 1e-5f);
    float q0 = fmaxf((v.x - mu) * rstd * gg[2 * tid] + bbv[2 * tid], 0.f);
    float q1 = fmaxf((v.y - mu) * rstd * gg[2 * tid + 1] + bbv[2 * tid + 1], 0.f);
    q[2 * tid] = q0;
    q[2 * tid + 1] = q1;
    *(float2*)&g_xbuf[b * 3072 + 1024 + 2 * tid] = make_float2(q0, q1);
    __syncthreads();

    // attention: warp wid handles head wid
    const int hh = wid;
    const int L = step + 1;
    const float* qh = q + hh * HD;
    float msc[4], m = -1e30f;
#pragma unroll
    for (int i = 0; i < 4; i++) {
        int c = lane + i * 32;
        float d = -1e30f;
        if (c < L) {
            const float* kr = g_kcache + ((size_t)c * BB + b) * NHID + hh * HD;
            float acc = 0.f;
#pragma unroll
            for (int j = 0; j < 16; j++) {
                float4 kv = *(const float4*)&kr[j * 4];
                acc += qh[j * 4] * kv.x + qh[j * 4 + 1] * kv.y +
                       qh[j * 4 + 2] * kv.z + qh[j * 4 + 3] * kv.w;
            }
            d = acc * 0.125f;
        }
        msc[i] = d;
        m = fmaxf(m, d);
    }
#pragma unroll
    for (int o = 16; o; o >>= 1) m = fmaxf(m, __shfl_xor_sync(0xffffffffu, m, o));
    float se = 0.f;
#pragma unroll
    for (int i = 0; i < 4; i++) {
        float e = expf(msc[i] - m);   // c >= L -> exp(-huge) = 0
        sc[hh][lane + i * 32] = e;
        se += e;
    }
#pragma unroll
    for (int o = 16; o; o >>= 1) se += __shfl_xor_sync(0xffffffffu, se, o);
    float inv = 1.f / se;
    __syncwarp();

    // weighted V sum: lane owns dims 2*lane, 2*lane+1
    float o0 = 0.f, o1 = 0.f;
    const float* vbase = g_vcache + (size_t)b * NHID + hh * HD + 2 * lane;
#pragma unroll 4
    for (int c = 0; c < L; c++) {
        float wgt = sc[hh][c];
        float2 vv = *(const float2*)(vbase + (size_t)c * BB * NHID);
        o0 += wgt * vv.x;
        o1 += wgt * vv.y;
    }
    *(float2*)&g_xbuf[b * 3072 + 2048 + hh * HD + 2 * lane] = make_float2(o0 * inv, o1 * inv);
}

// ---------------- decoder GEMM (round-4 verbatim): logits = states @ dec_w.T + dec_b ------
__global__ __launch_bounds__(256, 1) void k_dec(const float* __restrict__ A,
                                                const float* __restrict__ Wd,
                                                const float* __restrict__ bias,
                                                float* __restrict__ out) {
    __shared__ unsigned ah[128][20], al[128][20], bh_[128][20], bl_[128][20];
    int tid = threadIdx.x;
    int mb = blockIdx.x * 128, nb = blockIdx.y * 128;
    int w = tid >> 5, lane = tid & 31, g = lane >> 2, tig = lane & 3;
    int mw = w >> 2, nw = w & 3;  // 2 m-warps x 4 n-warps
    float acc[4][4][4] = {};
    float4 aa[4], wv[4];

    auto load = [&](int kc) {
#pragma unroll
        for (int i = 0; i < 4; i++) {
            int e = tid + i * 256;
            int r = e >> 3, cg = (e & 7) << 2;
            aa[i] = *(const float4*)(A + (size_t)(mb + r) * 1024 + kc + cg);
            wv[i] = *(const float4*)(Wd + (size_t)(nb + r) * 1024 + kc + cg);
        }
    };
    auto store = [&]() {
#pragma unroll
        for (int i = 0; i < 4; i++) {
            int e = tid + i * 256;
            int r = e >> 3, wd = (e & 7) * 2;
            cvtpair(aa[i], &ah[r][wd], &al[r][wd]);
            cvtpair(wv[i], &bh_[r][wd], &bl_[r][wd]);
        }
    };

    load(0);
    for (int c = 0; c < 32; c++) {
        store();
        __syncthreads();
        if (c < 31) load((c + 1) * 32);
#pragma unroll
        for (int s = 0; s < 2; s++) {
            int w0 = s * 8 + tig, w1 = w0 + 4;
            unsigned bh[4][2], bl[4][2];
#pragma unroll
            for (int nt = 0; nt < 4; nt++) {
                int col = nw * 32 + nt * 8 + g;
                bh[nt][0] = bh_[col][w0]; bh[nt][1] = bh_[col][w1];
                bl[nt][0] = bl_[col][w0]; bl[nt][1] = bl_[col][w1];
            }
#pragma unroll
            for (int mt = 0; mt < 4; mt++) {
                int r0 = mw * 64 + mt * 16 + g;
                unsigned a0 = ah[r0][w0], a1 = ah[r0 + 8][w0], a2 = ah[r0][w1], a3 = ah[r0 + 8][w1];
                unsigned l0 = al[r0][w0], l1 = al[r0 + 8][w0], l2 = al[r0][w1], l3 = al[r0 + 8][w1];
#pragma unroll
                for (int nt = 0; nt < 4; nt++) {
                    mmabf(acc[mt][nt], a0, a1, a2, a3, bh[nt][0], bh[nt][1]);
                    mmabf(acc[mt][nt], a0, a1, a2, a3, bl[nt][0], bl[nt][1]);
                    mmabf(acc[mt][nt], l0, l1, l2, l3, bh[nt][0], bh[nt][1]);
                }
            }
        }
        __syncthreads();
    }
#pragma unroll
    for (int mt = 0; mt < 4; mt++) {
        int r0 = mb + mw * 64 + mt * 16 + g;
#pragma unroll
        for (int nt = 0; nt < 4; nt++) {
            int c0 = nb + nw * 32 + nt * 8 + 2 * tig;
            float2 bv = *(const float2*)&bias[c0];
            *(float2*)&out[(size_t)r0 * VV + c0] =
                make_float2(acc[mt][nt][0] + bv.x, acc[mt][nt][1] + bv.y);
            *(float2*)&out[(size_t)(r0 + 8) * VV + c0] =
                make_float2(acc[mt][nt][2] + bv.x, acc[mt][nt][3] + bv.y);
        }
    }
}

// ---------------- launch ----------------
extern "C" void kernel_launch(void* const* d_in, const int* in_sizes, int n_in,
                              void* d_out, int out_size) {
    (void)in_sizes; (void)n_in; (void)out_size;
    const int* obs = (const int*)d_in[0];
    const float* hidden_init = (const float*)d_in[1];
    const float* kinit = (const float*)d_in[2];
    const float* vinit = (const float*)d_in[3];
    const float* enc_w = (const float*)d_in[4];
    const float* q_w = (const float*)d_in[5];
    const float* q_b = (const float*)d_in[6];
    const float* qn_g = (const float*)d_in[7];
    const float* qn_b = (const float*)d_in[8];
    const float* int_w = (const float*)d_in[9];
    const float* int_b = (const float*)d_in[10];
    const float* intn_g = (const float*)d_in[11];
    const float* intn_b = (const float*)d_in[12];
    const float* fin_w = (const float*)d_in[13];
    const float* fin_b = (const float*)d_in[14];
    const float* fn_g = (const float*)d_in[15];
    const float* fn_b = (const float*)d_in[16];
    const float* dec_w = (const float*)d_in[17];
    const float* dec_b = (const float*)d_in[18];

    float* logits = (float*)d_out;
    float* states_full = logits + (size_t)SS * BB * VV;

    k_init<<<BB, 256>>>(hidden_init, kinit, vinit, states_full);
    k_embed<<<SS * BB, 256>>>(obs, enc_w);

    for (int s = 0; s < SS; s++) {
        // q = relu(ln([e,hidden] @ q_w.T + q_b)) -- LN fused into attention kernel
        k_gemm_step<<<dim3(16, KSPLIT), 256>>>(s, 0, q_w, 2048, 2048 / KSPLIT, 1024, 0,
                                               0, s, nullptr, nullptr, nullptr, nullptr);
        k_lnq_attn<<<BB, 512>>>(q_b, qn_g, qn_b, s);
        // inter = relu(ln([e,q,attn,hidden] @ int_w.T + int_b)); LN fused as epilogue
        k_gemm_step<<<dim3(64, KSPLIT), 256>>>(s, 0, int_w, 4096, 4096 / KSPLIT, 4096, 1,
                                               1, s, int_b, intn_g, intn_b, nullptr);
        // final = relu(ln(inter @ fin_w.T + fin_b)) -> split k,v,h; LN fused as epilogue
        k_gemm_step<<<dim3(48, KSPLIT), 256>>>(-1, 1, fin_w, 4096, 4096 / KSPLIT, 3072, 0,
                                               2, s, fin_b, fn_g, fn_b, states_full);
    }

    // logits = states @ dec_w.T + dec_b  (states = states_full rows 1..S)
    k_dec<<<dim3(32, VV / 128), 256>>>(states_full + BB * NHID, dec_w, dec_b, logits);
}

// round 8
// speedup vs baseline: 1.0991x; 1.0315x over previous
#include <cuda_runtime.h>
#include <math.h>

#define SS 128
#define BB 32
#define VV 32000
#define NINP 1024
#define NHID 1024
#define NHEADS 16
#define HD 64
#define KS 4   // split-K for persistent phases

// ---------------- device scratch ----------------
static __device__ float g_emb[(size_t)SS * BB * NINP];
static __device__ float g_xbuf[BB * 3072];                   // [hidden|q|attn]
static __device__ float g_kcache[(size_t)(SS + 1) * BB * NHID];
static __device__ float g_vcache[(size_t)(SS + 1) * BB * NHID];
static __device__ float g_inter[BB * 4096];
static __device__ float g_part[KS * BB * 4096];
static __device__ unsigned g_bar;

// ---------------- helpers ----------------
__device__ __forceinline__ unsigned packbf(float e, float o) {
    unsigned r;
    asm("cvt.rn.bf16x2.f32 %0, %1, %2;" : "=r"(r) : "f"(o), "f"(e));
    return r;
}
__device__ __forceinline__ void cvtpair(float4 v, unsigned* ph, unsigned* pl) {
    unsigned h0 = packbf(v.x, v.y);
    unsigned h1 = packbf(v.z, v.w);
    float r0 = v.x - __uint_as_float(h0 << 16);
    float r1 = v.y - __uint_as_float(h0 & 0xffff0000u);
    float r2 = v.z - __uint_as_float(h1 << 16);
    float r3 = v.w - __uint_as_float(h1 & 0xffff0000u);
    ph[0] = h0; ph[1] = h1;
    pl[0] = packbf(r0, r1);
    pl[1] = packbf(r2, r3);
}
__device__ __forceinline__ void mmabf(float* c, unsigned a0, unsigned a1, unsigned a2,
                                      unsigned a3, unsigned b0, unsigned b1) {
    asm volatile(
        "mma.sync.aligned.m16n8k16.row.col.f32.bf16.bf16.f32 "
        "{%0,%1,%2,%3},{%4,%5,%6,%7},{%8,%9},{%0,%1,%2,%3};"
        : "+f"(c[0]), "+f"(c[1]), "+f"(c[2]), "+f"(c[3])
        : "r"(a0), "r"(a1), "r"(a2), "r"(a3), "r"(b0), "r"(b1));
}

// grid-wide barrier: deadlock-safe because grid = 2*SMs and __launch_bounds__(256,2)
// guarantees 2 resident blocks/SM.
__device__ __forceinline__ void gridbar(unsigned target) {
    __threadfence();
    __syncthreads();
    if (threadIdx.x == 0) {
        atomicAdd(&g_bar, 1u);
        while (*(volatile unsigned*)&g_bar < target) __nanosleep(64);
    }
    __syncthreads();
}

// ---------------- setup ----------------
__global__ void k_init(const float* __restrict__ h0, const float* __restrict__ kc0,
                       const float* __restrict__ vc0, float* __restrict__ states_full) {
    int b = blockIdx.x, t = threadIdx.x;
    if (b == 0 && t == 0) g_bar = 0u;
    float4 h = ((const float4*)(h0 + b * NHID))[t];
    ((float4*)(g_xbuf + b * 3072))[t] = h;
    ((float4*)(states_full + (size_t)b * NHID))[t] = h;
    ((float4*)(g_kcache + (size_t)b * NHID))[t] = ((const float4*)(kc0 + b * NHID))[t];
    ((float4*)(g_vcache + (size_t)b * NHID))[t] = ((const float4*)(vc0 + b * NHID))[t];
}

__global__ void k_embed(const int* __restrict__ obs, const float* __restrict__ enc_w) {
    int idx = blockIdx.x;
    int row = obs[idx];
    ((float4*)(g_emb + (size_t)idx * NINP))[threadIdx.x] =
        ((const float4*)(enc_w + (size_t)row * NINP))[threadIdx.x];
}

// ---------------- GEMM tile (round-4 mainloop; x via __ldcg) ----------------
__device__ __forceinline__ void gemm_tile(int nb, int kidx, int estep, int xsel,
                                          const float* __restrict__ W, int K, int klen,
                                          int N, int permute, unsigned* sm) {
    unsigned (*xh)[36] = (unsigned(*)[36])sm;
    unsigned (*xl)[36] = (unsigned(*)[36])(sm + 1152);
    unsigned (*wh)[36] = (unsigned(*)[36])(sm + 2304);
    unsigned (*wl)[36] = (unsigned(*)[36])(sm + 4608);
    const int tid = threadIdx.x;
    const int k0 = kidx * klen;
    const int w = tid >> 5, lane = tid & 31, g = lane >> 2, tig = lane & 3;

    const float* xe = g_emb + (size_t)(estep > 0 ? estep : 0) * BB * NINP;
    const int ecols = (estep >= 0) ? NINP : 0;
    const float* xr = xsel ? g_inter : g_xbuf;
    const int xstride = xsel ? 4096 : 3072;

    float acc[2][4] = {};
    float4 xa[2], wa[4];

    auto loadx = [&](int kc) {
#pragma unroll
        for (int i = 0; i < 2; i++) {
            int e = tid + i * 256;
            int r = e >> 4, cg = (e & 15) << 2;
            int gc = kc + cg;
            const float* src = (gc < ecols) ? (xe + r * NINP + gc)
                                            : (xr + r * xstride + (gc - ecols));
            xa[i] = __ldcg((const float4*)src);
        }
#pragma unroll
        for (int i = 0; i < 4; i++) {
            int e = tid + i * 256;
            int r = e >> 4, cg = (e & 15) << 2;
            int gc = kc + cg;
            int wc = gc;
            if (permute) wc = (gc < 1024) ? gc : ((gc < 2048) ? gc + 2048 : gc - 1024);
            wa[i] = *(const float4*)(W + (size_t)(nb + r) * K + wc);
        }
    };
    auto store = [&]() {
#pragma unroll
        for (int i = 0; i < 2; i++) {
            int e = tid + i * 256;
            int r = e >> 4, wd = (e & 15) * 2;
            cvtpair(xa[i], &xh[r][wd], &xl[r][wd]);
        }
#pragma unroll
        for (int i = 0; i < 4; i++) {
            int e = tid + i * 256;
            int r = e >> 4, wd = (e & 15) * 2;
            cvtpair(wa[i], &wh[r][wd], &wl[r][wd]);
        }
    };

    const int nchunks = klen >> 6;
    loadx(k0);
    for (int c = 0; c < nchunks; c++) {
        store();
        __syncthreads();
        if (c + 1 < nchunks) loadx(k0 + (c + 1) * 64);
#pragma unroll
        for (int s = 0; s < 4; s++) {
            int w0 = s * 8 + tig, w1 = w0 + 4;
            unsigned bh0 = wh[w * 8 + g][w0], bh1 = wh[w * 8 + g][w1];
            unsigned bl0 = wl[w * 8 + g][w0], bl1 = wl[w * 8 + g][w1];
#pragma unroll
            for (int mt = 0; mt < 2; mt++) {
                int r0 = mt * 16 + g;
                unsigned ah0 = xh[r0][w0], ah1 = xh[r0 + 8][w0];
                unsigned ah2 = xh[r0][w1], ah3 = xh[r0 + 8][w1];
                unsigned al0 = xl[r0][w0], al1 = xl[r0 + 8][w0];
                unsigned al2 = xl[r0][w1], al3 = xl[r0 + 8][w1];
                mmabf(acc[mt], ah0, ah1, ah2, ah3, bh0, bh1);
                mmabf(acc[mt], ah0, ah1, ah2, ah3, bl0, bl1);
                mmabf(acc[mt], al0, al1, al2, al3, bh0, bh1);
            }
        }
        __syncthreads();
    }
    float* p = g_part + (size_t)kidx * 32 * N;
    int n0 = nb + w * 8 + 2 * tig;
#pragma unroll
    for (int mt = 0; mt < 2; mt++) {
        int r0 = mt * 16 + g;
        *(float2*)&p[r0 * N + n0] = make_float2(acc[mt][0], acc[mt][1]);
        *(float2*)&p[(r0 + 8) * N + n0] = make_float2(acc[mt][2], acc[mt][3]);
    }
}

// ---------------- attention block (64 blocks: b = bid>>1, 8 heads per block) -------------
__device__ __forceinline__ void attn_block(int bid, const float* __restrict__ qb,
                                           const float* __restrict__ gg,
                                           const float* __restrict__ bbv, int step,
                                           float* sm) {
    float* q = sm;                 // 1024
    float* sc8 = sm + 1024;        // [8][160]
    float* r1 = sm + 1024 + 1280;  // 8
    float* r2 = r1 + 8;
    const int b = bid >> 1, half = bid & 1;
    const int tid = threadIdx.x, lane = tid & 31, w = tid >> 5;
    const int c0 = 4 * tid;

    float4 v = *(const float4*)(qb + c0);
#pragma unroll
    for (int j = 0; j < KS; j++) {
        float4 p = __ldcg((const float4*)(g_part + (size_t)j * 32 * 1024 + b * 1024 + c0));
        v.x += p.x; v.y += p.y; v.z += p.z; v.w += p.w;
    }
    float s1 = v.x + v.y + v.z + v.w;
    float s2 = v.x * v.x + v.y * v.y + v.z * v.z + v.w * v.w;
#pragma unroll
    for (int o = 16; o; o >>= 1) {
        s1 += __shfl_xor_sync(0xffffffffu, s1, o);
        s2 += __shfl_xor_sync(0xffffffffu, s2, o);
    }
    if (lane == 0) { r1[w] = s1; r2[w] = s2; }
    __syncthreads();
    s1 = 0.f; s2 = 0.f;
#pragma unroll
    for (int i = 0; i < 8; i++) { s1 += r1[i]; s2 += r2[i]; }
    float mu = s1 * (1.f / 1024.f);
    float rstd = rsqrtf(s2 * (1.f / 1024.f) - mu * mu + 1e-5f);
    float qv0 = fmaxf((v.x - mu) * rstd * gg[c0] + bbv[c0], 0.f);
    float qv1 = fmaxf((v.y - mu) * rstd * gg[c0 + 1] + bbv[c0 + 1], 0.f);
    float qv2 = fmaxf((v.z - mu) * rstd * gg[c0 + 2] + bbv[c0 + 2], 0.f);
    float qv3 = fmaxf((v.w - mu) * rstd * gg[c0 + 3] + bbv[c0 + 3], 0.f);
    *(float4*)&q[c0] = make_float4(qv0, qv1, qv2, qv3);
    if ((c0 >> 9) == half)
        *(float4*)&g_xbuf[b * 3072 + 1024 + c0] = make_float4(qv0, qv1, qv2, qv3);
    __syncthreads();

    const int h = half * 8 + w;
    const int L = step + 1;
    const float* qh = q + h * HD;
    float msc[5], m = -1e30f;
#pragma unroll
    for (int i = 0; i < 5; i++) {
        int c = lane + i * 32;
        float d = -1e30f;
        if (c < L) {
            const float* kr = g_kcache + ((size_t)c * BB + b) * NHID + h * HD;
            float acc = 0.f;
#pragma unroll
            for (int j = 0; j < 16; j++) {
                float4 kv = __ldcg((const float4*)&kr[j * 4]);
                acc += qh[j * 4] * kv.x + qh[j * 4 + 1] * kv.y +
                       qh[j * 4 + 2] * kv.z + qh[j * 4 + 3] * kv.w;
            }
            d = acc * 0.125f;
        }
        msc[i] = d;
        m = fmaxf(m, d);
    }
#pragma unroll
    for (int o = 16; o; o >>= 1) m = fmaxf(m, __shfl_xor_sync(0xffffffffu, m, o));
    float se = 0.f;
#pragma unroll
    for (int i = 0; i < 5; i++) {
        float e = expf(msc[i] - m);
        sc8[w * 160 + lane + i * 32] = e;
        se += e;
    }
#pragma unroll
    for (int o = 16; o; o >>= 1) se += __shfl_xor_sync(0xffffffffu, se, o);
    float inv = 1.f / se;
    __syncwarp();

    float o0 = 0.f, o1 = 0.f;
    const float* vbase = g_vcache + (size_t)b * NHID + h * HD + 2 * lane;
#pragma unroll 4
    for (int c = 0; c < L; c++) {
        float wgt = sc8[w * 160 + c];
        float2 vv = __ldcg((const float2*)(vbase + (size_t)c * BB * NHID));
        o0 += wgt * vv.x;
        o1 += wgt * vv.y;
    }
    *(float2*)&g_xbuf[b * 3072 + 2048 + h * HD + 2 * lane] = make_float2(o0 * inv, o1 * inv);
}

// ---------------- LN blocks (32 blocks, one batch row each) ----------------
__device__ __forceinline__ void ln_int_block(int row, const float* __restrict__ bias,
                                             const float* __restrict__ gg,
                                             const float* __restrict__ bb2, float* sm) {
    float* pre = sm;
    float* r1 = sm + 4096;
    float* r2 = r1 + 8;
    const int tid = threadIdx.x, lane = tid & 31, w = tid >> 5;
    float s1 = 0.f, s2 = 0.f;
#pragma unroll
    for (int i = 0; i < 4; i++) {
        int c = (tid + i * 256) * 4;
        float4 v = *(const float4*)&bias[c];
#pragma unroll
        for (int j = 0; j < KS; j++) {
            float4 p = __ldcg((const float4*)&g_part[(size_t)j * 32 * 4096 + row * 4096 + c]);
            v.x += p.x; v.y += p.y; v.z += p.z; v.w += p.w;
        }
        *(float4*)&pre[c] = v;
        s1 += v.x + v.y + v.z + v.w;
        s2 += v.x * v.x + v.y * v.y + v.z * v.z + v.w * v.w;
    }
#pragma unroll
    for (int o = 16; o; o >>= 1) {
        s1 += __shfl_xor_sync(0xffffffffu, s1, o);
        s2 += __shfl_xor_sync(0xffffffffu, s2, o);
    }
    if (lane == 0) { r1[w] = s1; r2[w] = s2; }
    __syncthreads();
    s1 = 0.f; s2 = 0.f;
#pragma unroll
    for (int i = 0; i < 8; i++) { s1 += r1[i]; s2 += r2[i]; }
    float mu = s1 * (1.f / 4096.f);
    float rstd = rsqrtf(s2 * (1.f / 4096.f) - mu * mu + 1e-5f);
#pragma unroll
    for (int i = 0; i < 16; i++) {
        int c = tid + i * 256;
        g_inter[row * 4096 + c] = fmaxf((pre[c] - mu) * rstd * gg[c] + bb2[c], 0.f);
    }
}

__device__ __forceinline__ void ln_fin_block(int row, const float* __restrict__ bias,
                                             const float* __restrict__ gg,
                                             const float* __restrict__ bb2, int step,
                                             float* __restrict__ states_full, float* sm) {
    float* pre = sm;
    float* r1 = sm + 4096;
    float* r2 = r1 + 8;
    const int tid = threadIdx.x, lane = tid & 31, w = tid >> 5;
    float s1 = 0.f, s2 = 0.f;
#pragma unroll
    for (int i = 0; i < 3; i++) {
        int c = (tid + i * 256) * 4;
        float4 v = *(const float4*)&bias[c];
#pragma unroll
        for (int j = 0; j < KS; j++) {
            float4 p = __ldcg((const float4*)&g_part[(size_t)j * 32 * 3072 + row * 3072 + c]);
            v.x += p.x; v.y += p.y; v.z += p.z; v.w += p.w;
        }
        *(float4*)&pre[c] = v;
        s1 += v.x + v.y + v.z + v.w;
        s2 += v.x * v.x + v.y * v.y + v.z * v.z + v.w * v.w;
    }
#pragma unroll
    for (int o = 16; o; o >>= 1) {
        s1 += __shfl_xor_sync(0xffffffffu, s1, o);
        s2 += __shfl_xor_sync(0xffffffffu, s2, o);
    }
    if (lane == 0) { r1[w] = s1; r2[w] = s2; }
    __syncthreads();
    s1 = 0.f; s2 = 0.f;
#pragma unroll
    for (int i = 0; i < 8; i++) { s1 += r1[i]; s2 += r2[i]; }
    float mu = s1 * (1.f / 3072.f);
    float rstd = rsqrtf(s2 * (1.f / 3072.f) - mu * mu + 1e-5f);
#pragma unroll
    for (int i = 0; i < 12; i++) {
        int c = tid + i * 256;
        float y = fmaxf((pre[c] - mu) * rstd * gg[c] + bb2[c], 0.f);
        if (c < 1024) {
            g_kcache[((size_t)(step + 1) * BB + row) * NHID + c] = y;
        } else if (c < 2048) {
            g_vcache[((size_t)(step + 1) * BB + row) * NHID + (c - 1024)] = y;
        } else {
            int d = c - 2048;
            states_full[((size_t)(step + 1) * BB + row) * NHID + d] = y;
            g_xbuf[row * 3072 + d] = y;
        }
    }
}

// ---------------- persistent step loop: ONE kernel for all 128 steps ----------------
__global__ __launch_bounds__(256, 2) void k_steps(
    const float* __restrict__ q_w, const float* __restrict__ q_b,
    const float* __restrict__ qn_g, const float* __restrict__ qn_b,
    const float* __restrict__ int_w, const float* __restrict__ int_b,
    const float* __restrict__ intn_g, const float* __restrict__ intn_b,
    const float* __restrict__ fin_w, const float* __restrict__ fin_b,
    const float* __restrict__ fn_g, const float* __restrict__ fn_b,
    float* __restrict__ states_full) {
    __shared__ unsigned sm[6912];   // 27648 B, unioned across phases
    const unsigned G = gridDim.x;
    const int bid = blockIdx.x;
    unsigned ep = 0;

    for (int s = 0; s < SS; s++) {
        // Phase 1: q GEMM (16 n-tiles x 4 splits = 64 tiles)
        for (int t = bid; t < 64; t += (int)G)
            gemm_tile((t >> 2) * 64, t & 3, s, 0, q_w, 2048, 512, 1024, 0, sm);
        ep++; gridbar(ep * G);
        // Phase 2: LN(q) + attention (64 blocks)
        if (bid < 64) attn_block(bid, q_b, qn_g, qn_b, s, (float*)sm);
        ep++; gridbar(ep * G);
        // Phase 3: int GEMM (64 x 4 = 256 tiles)
        for (int t = bid; t < 256; t += (int)G)
            gemm_tile((t >> 2) * 64, t & 3, s, 0, int_w, 4096, 1024, 4096, 1, sm);
        ep++; gridbar(ep * G);
        // Phase 4: LN(int)
        if (bid < 32) ln_int_block(bid, int_b, intn_g, intn_b, (float*)sm);
        ep++; gridbar(ep * G);
        // Phase 5: fin GEMM (48 x 4 = 192 tiles)
        for (int t = bid; t < 192; t += (int)G)
            gemm_tile((t >> 2) * 64, t & 3, -1, 1, fin_w, 4096, 1024, 3072, 0, sm);
        ep++; gridbar(ep * G);
        // Phase 6: LN(fin) -> caches/states/hidden
        if (bid < 32) ln_fin_block(bid, fin_b, fn_g, fn_b, s, states_full, (float*)sm);
        ep++; gridbar(ep * G);
    }
}

// ---------------- decoder GEMM (round-4 verbatim) ----------------
__global__ __launch_bounds__(256, 1) void k_dec(const float* __restrict__ A,
                                                const float* __restrict__ Wd,
                                                const float* __restrict__ bias,
                                                float* __restrict__ out) {
    __shared__ unsigned ah[128][20], al[128][20], bh_[128][20], bl_[128][20];
    int tid = threadIdx.x;
    int mb = blockIdx.x * 128, nb = blockIdx.y * 128;
    int w = tid >> 5, lane = tid & 31, g = lane >> 2, tig = lane & 3;
    int mw = w >> 2, nw = w & 3;
    float acc[4][4][4] = {};
    float4 aa[4], wv[4];

    auto load = [&](int kc) {
#pragma unroll
        for (int i = 0; i < 4; i++) {
            int e = tid + i * 256;
            int r = e >> 3, cg = (e & 7) << 2;
            aa[i] = *(const float4*)(A + (size_t)(mb + r) * 1024 + kc + cg);
            wv[i] = *(const float4*)(Wd + (size_t)(nb + r) * 1024 + kc + cg);
        }
    };
    auto store = [&]() {
#pragma unroll
        for (int i = 0; i < 4; i++) {
            int e = tid + i * 256;
            int r = e >> 3, wd = (e & 7) * 2;
            cvtpair(aa[i], &ah[r][wd], &al[r][wd]);
            cvtpair(wv[i], &bh_[r][wd], &bl_[r][wd]);
        }
    };

    load(0);
    for (int c = 0; c < 32; c++) {
        store();
        __syncthreads();
        if (c < 31) load((c + 1) * 32);
#pragma unroll
        for (int s = 0; s < 2; s++) {
            int w0 = s * 8 + tig, w1 = w0 + 4;
            unsigned bh[4][2], bl[4][2];
#pragma unroll
            for (int nt = 0; nt < 4; nt++) {
                int col = nw * 32 + nt * 8 + g;
                bh[nt][0] = bh_[col][w0]; bh[nt][1] = bh_[col][w1];
                bl[nt][0] = bl_[col][w0]; bl[nt][1] = bl_[col][w1];
            }
#pragma unroll
            for (int mt = 0; mt < 4; mt++) {
                int r0 = mw * 64 + mt * 16 + g;
                unsigned a0 = ah[r0][w0], a1 = ah[r0 + 8][w0], a2 = ah[r0][w1], a3 = ah[r0 + 8][w1];
                unsigned l0 = al[r0][w0], l1 = al[r0 + 8][w0], l2 = al[r0][w1], l3 = al[r0 + 8][w1];
#pragma unroll
                for (int nt = 0; nt < 4; nt++) {
                    mmabf(acc[mt][nt], a0, a1, a2, a3, bh[nt][0], bh[nt][1]);
                    mmabf(acc[mt][nt], a0, a1, a2, a3, bl[nt][0], bl[nt][1]);
                    mmabf(acc[mt][nt], l0, l1, l2, l3, bh[nt][0], bh[nt][1]);
                }
            }
        }
        __syncthreads();
    }
#pragma unroll
    for (int mt = 0; mt < 4; mt++) {
        int r0 = mb + mw * 64 + mt * 16 + g;
#pragma unroll
        for (int nt = 0; nt < 4; nt++) {
            int c0 = nb + nw * 32 + nt * 8 + 2 * tig;
            float2 bv = *(const float2*)&bias[c0];
            *(float2*)&out[(size_t)r0 * VV + c0] =
                make_float2(acc[mt][nt][0] + bv.x, acc[mt][nt][1] + bv.y);
            *(float2*)&out[(size_t)(r0 + 8) * VV + c0] =
                make_float2(acc[mt][nt][2] + bv.x, acc[mt][nt][3] + bv.y);
        }
    }
}

// ---------------- launch ----------------
extern "C" void kernel_launch(void* const* d_in, const int* in_sizes, int n_in,
                              void* d_out, int out_size) {
    (void)in_sizes; (void)n_in; (void)out_size;
    const int* obs = (const int*)d_in[0];
    const float* hidden_init = (const float*)d_in[1];
    const float* kinit = (const float*)d_in[2];
    const float* vinit = (const float*)d_in[3];
    const float* enc_w = (const float*)d_in[4];
    const float* q_w = (const float*)d_in[5];
    const float* q_b = (const float*)d_in[6];
    const float* qn_g = (const float*)d_in[7];
    const float* qn_b = (const float*)d_in[8];
    const float* int_w = (const float*)d_in[9];
    const float* int_b = (const float*)d_in[10];
    const float* intn_g = (const float*)d_in[11];
    const float* intn_b = (const float*)d_in[12];
    const float* fin_w = (const float*)d_in[13];
    const float* fin_b = (const float*)d_in[14];
    const float* fn_g = (const float*)d_in[15];
    const float* fn_b = (const float*)d_in[16];
    const float* dec_w = (const float*)d_in[17];
    const float* dec_b = (const float*)d_in[18];

    float* logits = (float*)d_out;
    float* states_full = logits + (size_t)SS * BB * VV;

    int sms = 0;
    cudaDeviceGetAttribute(&sms, cudaDevAttrMultiProcessorCount, 0);
    int G = 2 * sms;   // co-resident by __launch_bounds__(256, 2)

    k_init<<<BB, 256>>>(hidden_init, kinit, vinit, states_full);
    k_embed<<<SS * BB, 256>>>(obs, enc_w);
    k_steps<<<G, 256>>>(q_w, q_b, qn_g, qn_b, int_w, int_b, intn_g, intn_b,
                        fin_w, fin_b, fn_g, fn_b, states_full);
    k_dec<<<dim3(32, VV / 128), 256>>>(states_full + BB * NHID, dec_w, dec_b, logits);
}

// round 10
// speedup vs baseline: 1.1431x; 1.0400x over previous
#include <cuda_runtime.h>
#include <math.h>

#define SS 128
#define BB 32
#define VV 32000
#define NINP 1024
#define NHID 1024
#define NHEADS 16
#define HD 64
#define KSPLIT 8

// ---------------- blobs: bf16 hi/lo pre-laid-out smem images ----------------
// Units: 1 uint4 = 4 words (32-bit). All offsets below are in WORDS unless noted.
// weight chunk image: [wh 64x36][wl 64x36] = 4608 words = 1152 uint4
static __device__ uint4 g_wq[(size_t)16 * 32 * 1152];    // q_w   [1024][2048]
static __device__ uint4 g_wi[(size_t)64 * 64 * 1152];    // int_w [4096][4096] (permuted)
static __device__ uint4 g_wf[(size_t)48 * 64 * 1152];    // fin_w [3072][4096]
static __device__ uint4 g_wd[(size_t)500 * 16 * 1152];   // dec_w [32000][1024]
// x chunk image: [xh 32x36][xl 32x36] = 2304 words = 576 uint4
static __device__ uint4 g_eimg[(size_t)SS * 16 * 576];   // embeddings, per step
static __device__ uint4 g_ximg[(size_t)64 * 576];        // chunks 16-31 hidden, 32-47 q, 48-63 attn
static __device__ uint4 g_iimg[(size_t)64 * 576];        // inter
// decoder A chunk image: [ah 128x36][al 128x36] = 9216 words = 2304 uint4
static __device__ uint4 g_aimg[(size_t)32 * 16 * 2304];  // states rows (32 mb x 16 gc)
static __device__ float g_kcache[(size_t)(SS + 1) * BB * NHID];
static __device__ float g_vcache[(size_t)(SS + 1) * BB * NHID];
static __device__ float g_part[KSPLIT * BB * 4096];

// ---------------- helpers ----------------
__device__ __forceinline__ unsigned packbf(float e, float o) {
    unsigned r;
    asm("cvt.rn.bf16x2.f32 %0, %1, %2;" : "=r"(r) : "f"(o), "f"(e));
    return r;
}
__device__ __forceinline__ void splitpair(float v0, float v1, unsigned& h, unsigned& l) {
    h = packbf(v0, v1);
    float r0 = v0 - __uint_as_float(h << 16);
    float r1 = v1 - __uint_as_float(h & 0xffff0000u);
    l = packbf(r0, r1);
}
__device__ __forceinline__ void mmabf(float* c, unsigned a0, unsigned a1, unsigned a2,
                                      unsigned a3, unsigned b0, unsigned b1) {
    asm volatile(
        "mma.sync.aligned.m16n8k16.row.col.f32.bf16.bf16.f32 "
        "{%0,%1,%2,%3},{%4,%5,%6,%7},{%8,%9},{%0,%1,%2,%3};"
        : "+f"(c[0]), "+f"(c[1]), "+f"(c[2]), "+f"(c[3])
        : "r"(a0), "r"(a1), "r"(a2), "r"(a3), "r"(b0), "r"(b1));
}
__device__ __forceinline__ void cp_commit() { asm volatile("cp.async.commit_group;"); }
template <int N>
__device__ __forceinline__ void cp_wait() { asm volatile("cp.async.wait_group %0;" ::"n"(N)); }
#define CPA16(d, s) asm volatile("cp.async.cg.shared.global [%0], [%1], 16;" ::"r"(d), "l"(s))

// ---------------- one-time weight conversion into blob layout ----------------
__global__ void k_cvt_w(const float* __restrict__ src, unsigned* __restrict__ dst,
                        int N, int K, int permute) {
    long total = (long)N * (K >> 1);
    long stride = (long)gridDim.x * blockDim.x;
    int KC = K >> 6;
    for (long i = (long)blockIdx.x * blockDim.x + threadIdx.x; i < total; i += stride) {
        int n = (int)(i / (K >> 1));
        int kw = (int)(i - (long)n * (K >> 1));
        int k = 2 * kw;
        int kk = k;
        if (permute) kk = (k < 1024) ? k : ((k < 2048) ? k + 2048 : k - 1024);
        float2 v = *(const float2*)(src + (size_t)n * K + kk);
        unsigned h, l;
        splitpair(v.x, v.y, h, l);
        int nt = n >> 6, r = n & 63, gc = kw >> 5, w = kw & 31;
        size_t base = ((size_t)nt * KC + gc) * 4608;   // words
        dst[base + r * 36 + w] = h;
        dst[base + 2304 + r * 36 + w] = l;
    }
}

// ---------------- setup ----------------
__global__ void k_embed(const int* __restrict__ obs, const float* __restrict__ enc_w) {
    int idx = blockIdx.x;           // s*B + b
    int s = idx >> 5, b = idx & 31;
    int row = obs[idx];
    int t = threadIdx.x;
    float4 v = ((const float4*)(enc_w + (size_t)row * NINP))[t];
    unsigned h0, l0, h1, l1;
    splitpair(v.x, v.y, h0, l0);
    splitpair(v.z, v.w, h1, l1);
    int d = 4 * t;
    unsigned* e = (unsigned*)g_eimg + ((size_t)(s * 16 + (d >> 6))) * 2304 + b * 36 + ((d & 63) >> 1);
    e[0] = h0; e[1] = h1;
    e[1152] = l0; e[1153] = l1;
}

__global__ void k_init(const float* __restrict__ h0v, const float* __restrict__ kc0,
                       const float* __restrict__ vc0, float* __restrict__ states_full) {
    int b = blockIdx.x, t = threadIdx.x;
    float4 h = ((const float4*)(h0v + b * NHID))[t];
    unsigned h0, l0, h1, l1;
    splitpair(h.x, h.y, h0, l0);
    splitpair(h.z, h.w, h1, l1);
    int d = 4 * t;
    unsigned* x = (unsigned*)g_ximg + ((size_t)(16 + (d >> 6))) * 2304 + b * 36 + ((d & 63) >> 1);
    x[0] = h0; x[1] = h1;
    x[1152] = l0; x[1153] = l1;
    ((float4*)(states_full + (size_t)b * NHID))[t] = h;
    ((float4*)(g_kcache + (size_t)b * NHID))[t] = ((const float4*)(kc0 + b * NHID))[t];
    ((float4*)(g_vcache + (size_t)b * NHID))[t] = ((const float4*)(vc0 + b * NHID))[t];
}

// ---------------- step GEMM: cp.async blobs -> smem, round-4 mma body ----------------
// xmode 0: chunks <16 from eimg[step], else ximg; xmode 1: iimg.
__global__ __launch_bounds__(256, 4) void k_gemm(int xmode, int sstep,
                                                 const uint4* __restrict__ wblob,
                                                 int KC, int CH, int N) {
    extern __shared__ uint4 dsm[];
    unsigned sb = (unsigned)__cvta_generic_to_shared(dsm);
    const int tid = threadIdx.x;
    const int nt = blockIdx.x, kidx = blockIdx.y;
    const int w = tid >> 5, lane = tid & 31, g = lane >> 2, tig = lane & 3;
    float acc[2][4] = {};

    auto issue = [&](int stage, int cc) {
        int gc = kidx * CH + cc;
        const uint4* wsrc = wblob + ((size_t)nt * KC + gc) * 1152;
        const uint4* xsrc;
        if (xmode) xsrc = g_iimg + (size_t)gc * 576;
        else if (gc < 16) xsrc = g_eimg + ((size_t)(sstep * 16 + gc)) * 576;
        else xsrc = g_ximg + (size_t)gc * 576;
        unsigned db = sb + stage * 27648;
        // 1728 uint4 per stage: x image (576) then w image (1152)
        for (int u = tid; u < 1728; u += 256) {
            const uint4* s_ = (u < 576) ? (xsrc + u) : (wsrc + (u - 576));
            CPA16(db + u * 16, s_);
        }
        cp_commit();
    };

    issue(0, 0);
    issue(1, 1);
    for (int cc = 0; cc < CH; cc++) {
        cp_wait<1>();
        __syncthreads();
        const unsigned* st = (const unsigned*)dsm + (cc & 1) * 6912;
        const unsigned* xh = st;
        const unsigned* xl = st + 1152;
        const unsigned* wh = st + 2304;
        const unsigned* wl = st + 4608;
#pragma unroll
        for (int s = 0; s < 4; s++) {
            int w0 = s * 8 + tig, w1 = w0 + 4;
            unsigned bh0 = wh[(w * 8 + g) * 36 + w0], bh1 = wh[(w * 8 + g) * 36 + w1];
            unsigned bl0 = wl[(w * 8 + g) * 36 + w0], bl1 = wl[(w * 8 + g) * 36 + w1];
#pragma unroll
            for (int mt = 0; mt < 2; mt++) {
                int r0 = mt * 16 + g;
                unsigned ah0 = xh[r0 * 36 + w0], ah1 = xh[(r0 + 8) * 36 + w0];
                unsigned ah2 = xh[r0 * 36 + w1], ah3 = xh[(r0 + 8) * 36 + w1];
                unsigned al0 = xl[r0 * 36 + w0], al1 = xl[(r0 + 8) * 36 + w0];
                unsigned al2 = xl[r0 * 36 + w1], al3 = xl[(r0 + 8) * 36 + w1];
                mmabf(acc[mt], ah0, ah1, ah2, ah3, bh0, bh1);
                mmabf(acc[mt], ah0, ah1, ah2, ah3, bl0, bl1);
                mmabf(acc[mt], al0, al1, al2, al3, bh0, bh1);
            }
        }
        __syncthreads();
        if (cc + 2 < CH) issue(cc & 1, cc + 2);
        else cp_commit();
    }
    float* p = g_part + (size_t)kidx * 32 * N;
    int n0 = nt * 64 + w * 8 + 2 * tig;
#pragma unroll
    for (int mt = 0; mt < 2; mt++) {
        int r0 = mt * 16 + g;
        *(float2*)&p[r0 * N + n0] = make_float2(acc[mt][0], acc[mt][1]);
        *(float2*)&p[(r0 + 8) * N + n0] = make_float2(acc[mt][2], acc[mt][3]);
    }
}

// ---------------- fused LN(q)+relu + attention; 32 blocks x 512 threads (warp=head) -----
__global__ __launch_bounds__(512) void k_lnq_attn(const float* __restrict__ qb,
                                                  const float* __restrict__ gg,
                                                  const float* __restrict__ bbv, int step) {
    __shared__ float q[1024];
    __shared__ float sc[NHEADS][132];
    __shared__ float r1[16], r2[16];
    int b = blockIdx.x, tid = threadIdx.x, lane = tid & 31, wid = tid >> 5;

    float2 v = *(const float2*)(qb + 2 * tid);
#pragma unroll
    for (int j = 0; j < KSPLIT; j++) {
        float2 p = *(const float2*)(g_part + (size_t)j * 32 * 1024 + b * 1024 + 2 * tid);
        v.x += p.x; v.y += p.y;
    }
    float s1 = v.x + v.y, s2 = v.x * v.x + v.y * v.y;
#pragma unroll
    for (int o = 16; o; o >>= 1) {
        s1 += __shfl_xor_sync(0xffffffffu, s1, o);
        s2 += __shfl_xor_sync(0xffffffffu, s2, o);
    }
    if (lane == 0) { r1[wid] = s1; r2[wid] = s2; }
    __syncthreads();
    s1 = 0.f; s2 = 0.f;
#pragma unroll
    for (int i = 0; i < 16; i++) { s1 += r1[i]; s2 += r2[i]; }
    float mu = s1 * (1.f / 1024.f);
    float rstd = rsqrtf(s2 * (1.f / 1024.f) - mu * mu + 1e-5f);
    float q0 = fmaxf((v.x - mu) * rstd * gg[2 * tid] + bbv[2 * tid], 0.f);
    float q1 = fmaxf((v.y - mu) * rstd * gg[2 * tid + 1] + bbv[2 * tid + 1], 0.f);
    q[2 * tid] = q0;
    q[2 * tid + 1] = q1;
    {
        unsigned h_, l_;
        splitpair(q0, q1, h_, l_);
        unsigned* x = (unsigned*)g_ximg + ((size_t)(32 + (tid >> 5))) * 2304 + b * 36 + (tid & 31);
        x[0] = h_;
        x[1152] = l_;
    }
    __syncthreads();

    const int hh = wid;
    const int L = step + 1;
    const float* qh = q + hh * HD;
    float msc[4], m = -1e30f;
#pragma unroll
    for (int i = 0; i < 4; i++) {
        int c = lane + i * 32;
        float d = -1e30f;
        if (c < L) {
            const float* kr = g_kcache + ((size_t)c * BB + b) * NHID + hh * HD;
            float acc = 0.f;
#pragma unroll
            for (int j = 0; j < 16; j++) {
                float4 kv = *(const float4*)&kr[j * 4];
                acc += qh[j * 4] * kv.x + qh[j * 4 + 1] * kv.y +
                       qh[j * 4 + 2] * kv.z + qh[j * 4 + 3] * kv.w;
            }
            d = acc * 0.125f;
        }
        msc[i] = d;
        m = fmaxf(m, d);
    }
#pragma unroll
    for (int o = 16; o; o >>= 1) m = fmaxf(m, __shfl_xor_sync(0xffffffffu, m, o));
    float se = 0.f;
#pragma unroll
    for (int i = 0; i < 4; i++) {
        float e = expf(msc[i] - m);
        sc[hh][lane + i * 32] = e;
        se += e;
    }
#pragma unroll
    for (int o = 16; o; o >>= 1) se += __shfl_xor_sync(0xffffffffu, se, o);
    float inv = 1.f / se;
    __syncwarp();

    float o0 = 0.f, o1 = 0.f;
    const float* vbase = g_vcache + (size_t)b * NHID + hh * HD + 2 * lane;
#pragma unroll 4
    for (int c = 0; c < L; c++) {
        float wgt = sc[hh][c];
        float2 vv = *(const float2*)(vbase + (size_t)c * BB * NHID);
        o0 += wgt * vv.x;
        o1 += wgt * vv.y;
    }
    o0 *= inv; o1 *= inv;
    unsigned oh, ol;
    splitpair(o0, o1, oh, ol);
    unsigned* x = (unsigned*)g_ximg + ((size_t)(48 + hh)) * 2304 + b * 36 + lane;
    x[0] = oh;
    x[1152] = ol;
}

// ---------------- LN(int)+relu -> iimg ----------------
__global__ __launch_bounds__(256) void k_ln_int(const float* __restrict__ bias,
                                                const float* __restrict__ gg,
                                                const float* __restrict__ bb2) {
    __shared__ float pre[4096];
    __shared__ float red1[8], red2[8];
    int b = blockIdx.x, tid = threadIdx.x, lane = tid & 31, wid = tid >> 5;
    float s1 = 0.f, s2 = 0.f;
#pragma unroll
    for (int i = 0; i < 4; i++) {
        int c = (tid + i * 256) * 4;
        float4 v = *(const float4*)&bias[c];
#pragma unroll
        for (int j = 0; j < KSPLIT; j++) {
            float4 p = *(const float4*)&g_part[(size_t)j * 32 * 4096 + b * 4096 + c];
            v.x += p.x; v.y += p.y; v.z += p.z; v.w += p.w;
        }
        *(float4*)&pre[c] = v;
        s1 += v.x + v.y + v.z + v.w;
        s2 += v.x * v.x + v.y * v.y + v.z * v.z + v.w * v.w;
    }
#pragma unroll
    for (int o = 16; o; o >>= 1) {
        s1 += __shfl_xor_sync(0xffffffffu, s1, o);
        s2 += __shfl_xor_sync(0xffffffffu, s2, o);
    }
    if (lane == 0) { red1[wid] = s1; red2[wid] = s2; }
    __syncthreads();
    s1 = 0.f; s2 = 0.f;
#pragma unroll
    for (int i = 0; i < 8; i++) { s1 += red1[i]; s2 += red2[i]; }
    float mu = s1 * (1.f / 4096.f);
    float rstd = rsqrtf(s2 * (1.f / 4096.f) - mu * mu + 1e-5f);
#pragma unroll
    for (int i = 0; i < 8; i++) {
        int c2 = 2 * (tid + i * 256);
        float y0 = fmaxf((pre[c2] - mu) * rstd * gg[c2] + bb2[c2], 0.f);
        float y1 = fmaxf((pre[c2 + 1] - mu) * rstd * gg[c2 + 1] + bb2[c2 + 1], 0.f);
        unsigned h_, l_;
        splitpair(y0, y1, h_, l_);
        unsigned* o = (unsigned*)g_iimg + ((size_t)(c2 >> 6)) * 2304 + b * 36 + ((c2 & 63) >> 1);
        o[0] = h_;
        o[1152] = l_;
    }
}

// ---------------- LN(fin)+relu -> kcache, vcache, states/aimg, hidden/ximg ----------------
__global__ __launch_bounds__(256) void k_ln_fin(const float* __restrict__ bias,
                                                const float* __restrict__ gg,
                                                const float* __restrict__ bb2, int step,
                                                float* __restrict__ states_full) {
    __shared__ float pre[3072];
    __shared__ float red1[8], red2[8];
    int b = blockIdx.x, tid = threadIdx.x, lane = tid & 31, wid = tid >> 5;
    float s1 = 0.f, s2 = 0.f;
#pragma unroll
    for (int i = 0; i < 3; i++) {
        int c = (tid + i * 256) * 4;
        float4 v = *(const float4*)&bias[c];
#pragma unroll
        for (int j = 0; j < KSPLIT; j++) {
            float4 p = *(const float4*)&g_part[(size_t)j * 32 * 3072 + b * 3072 + c];
            v.x += p.x; v.y += p.y; v.z += p.z; v.w += p.w;
        }
        *(float4*)&pre[c] = v;
        s1 += v.x + v.y + v.z + v.w;
        s2 += v.x * v.x + v.y * v.y + v.z * v.z + v.w * v.w;
    }
#pragma unroll
    for (int o = 16; o; o >>= 1) {
        s1 += __shfl_xor_sync(0xffffffffu, s1, o);
        s2 += __shfl_xor_sync(0xffffffffu, s2, o);
    }
    if (lane == 0) { red1[wid] = s1; red2[wid] = s2; }
    __syncthreads();
    s1 = 0.f; s2 = 0.f;
#pragma unroll
    for (int i = 0; i < 8; i++) { s1 += red1[i]; s2 += red2[i]; }
    float mu = s1 * (1.f / 3072.f);
    float rstd = rsqrtf(s2 * (1.f / 3072.f) - mu * mu + 1e-5f);
#pragma unroll
    for (int i = 0; i < 6; i++) {
        int c2 = 2 * (tid + i * 256);
        float y0 = fmaxf((pre[c2] - mu) * rstd * gg[c2] + bb2[c2], 0.f);
        float y1 = fmaxf((pre[c2 + 1] - mu) * rstd * gg[c2 + 1] + bb2[c2 + 1], 0.f);
        if (c2 < 1024) {
            *(float2*)&g_kcache[((size_t)(step + 1) * BB + b) * NHID + c2] = make_float2(y0, y1);
        } else if (c2 < 2048) {
            *(float2*)&g_vcache[((size_t)(step + 1) * BB + b) * NHID + (c2 - 1024)] =
                make_float2(y0, y1);
        } else {
            int d = c2 - 2048;
            *(float2*)&states_full[((size_t)(step + 1) * BB + b) * NHID + d] = make_float2(y0, y1);
            unsigned h_, l_;
            splitpair(y0, y1, h_, l_);
            unsigned* x = (unsigned*)g_ximg + ((size_t)(16 + (d >> 6))) * 2304 + b * 36 + ((d & 63) >> 1);
            x[0] = h_;
            x[1152] = l_;
            int ar = step * 32 + b;
            unsigned* a = (unsigned*)g_aimg + ((size_t)((ar >> 7) * 16 + (d >> 6))) * 9216 +
                          (ar & 127) * 36 + ((d & 63) >> 1);
            a[0] = h_;
            a[4608] = l_;
        }
    }
}

// ---------------- decoder: 128m x 64n tiles, cp.async blobs ----------------
__global__ __launch_bounds__(256, 2) void k_dec(const float* __restrict__ bias,
                                                float* __restrict__ out) {
    extern __shared__ uint4 dsm[];
    unsigned sb = (unsigned)__cvta_generic_to_shared(dsm);
    const int tid = threadIdx.x;
    const int mb = blockIdx.x, nbk = blockIdx.y;
    const int w = tid >> 5, lane = tid & 31, g = lane >> 2, tig = lane & 3;
    const int mw = w >> 1, nw = w & 1;
    float acc[2][4][4] = {};

    auto issue = [&](int stage, int gc) {
        const uint4* asrc = g_aimg + ((size_t)(mb * 16 + gc)) * 2304;
        const uint4* wsrc = g_wd + ((size_t)(nbk * 16 + gc)) * 1152;
        unsigned db = sb + stage * 55296;
        // 3456 uint4 per stage: A image (2304) then W image (1152)
        for (int u = tid; u < 3456; u += 256) {
            const uint4* s_ = (u < 2304) ? (asrc + u) : (wsrc + (u - 2304));
            CPA16(db + u * 16, s_);
        }
        cp_commit();
    };

    issue(0, 0);
    issue(1, 1);
    for (int cc = 0; cc < 16; cc++) {
        cp_wait<1>();
        __syncthreads();
        const unsigned* st = (const unsigned*)dsm + (cc & 1) * 13824;
        const unsigned* ah = st;
        const unsigned* al = st + 4608;
        const unsigned* wh = st + 9216;
        const unsigned* wl = st + 11520;
#pragma unroll
        for (int s = 0; s < 4; s++) {
            int w0 = s * 8 + tig, w1 = w0 + 4;
            unsigned bh[4][2], bl[4][2];
#pragma unroll
            for (int nt = 0; nt < 4; nt++) {
                int col = nw * 32 + nt * 8 + g;
                bh[nt][0] = wh[col * 36 + w0];
                bh[nt][1] = wh[col * 36 + w1];
                bl[nt][0] = wl[col * 36 + w0];
                bl[nt][1] = wl[col * 36 + w1];
            }
#pragma unroll
            for (int mt = 0; mt < 2; mt++) {
                int r0 = mw * 32 + mt * 16 + g;
                unsigned a0 = ah[r0 * 36 + w0], a1 = ah[(r0 + 8) * 36 + w0];
                unsigned a2 = ah[r0 * 36 + w1], a3 = ah[(r0 + 8) * 36 + w1];
                unsigned l0 = al[r0 * 36 + w0], l1 = al[(r0 + 8) * 36 + w0];
                unsigned l2 = al[r0 * 36 + w1], l3 = al[(r0 + 8) * 36 + w1];
#pragma unroll
                for (int nt = 0; nt < 4; nt++) {
                    mmabf(acc[mt][nt], a0, a1, a2, a3, bh[nt][0], bh[nt][1]);
                    mmabf(acc[mt][nt], a0, a1, a2, a3, bl[nt][0], bl[nt][1]);
                    mmabf(acc[mt][nt], l0, l1, l2, l3, bh[nt][0], bh[nt][1]);
                }
            }
        }
        __syncthreads();
        if (cc + 2 < 16) issue(cc & 1, cc + 2);
        else cp_commit();
    }
#pragma unroll
    for (int mt = 0; mt < 2; mt++) {
        int r0g = mb * 128 + mw * 32 + mt * 16 + g;
#pragma unroll
        for (int nt = 0; nt < 4; nt++) {
            int c0 = nbk * 64 + nw * 32 + nt * 8 + 2 * tig;
            float2 bv = *(const float2*)&bias[c0];
            *(float2*)&out[(size_t)r0g * VV + c0] =
                make_float2(acc[mt][nt][0] + bv.x, acc[mt][nt][1] + bv.y);
            *(float2*)&out[(size_t)(r0g + 8) * VV + c0] =
                make_float2(acc[mt][nt][2] + bv.x, acc[mt][nt][3] + bv.y);
        }
    }
}

// ---------------- launch ----------------
extern "C" void kernel_launch(void* const* d_in, const int* in_sizes, int n_in,
                              void* d_out, int out_size) {
    (void)in_sizes; (void)n_in; (void)out_size;
    const int* obs = (const int*)d_in[0];
    const float* hidden_init = (const float*)d_in[1];
    const float* kinit = (const float*)d_in[2];
    const float* vinit = (const float*)d_in[3];
    const float* enc_w = (const float*)d_in[4];
    const float* q_w = (const float*)d_in[5];
    const float* q_b = (const float*)d_in[6];
    const float* qn_g = (const float*)d_in[7];
    const float* qn_b = (const float*)d_in[8];
    const float* int_w = (const float*)d_in[9];
    const float* int_b = (const float*)d_in[10];
    const float* intn_g = (const float*)d_in[11];
    const float* intn_b = (const float*)d_in[12];
    const float* fin_w = (const float*)d_in[13];
    const float* fin_b = (const float*)d_in[14];
    const float* fn_g = (const float*)d_in[15];
    const float* fn_b = (const float*)d_in[16];
    const float* dec_w = (const float*)d_in[17];
    const float* dec_b = (const float*)d_in[18];

    float* logits = (float*)d_out;
    float* states_full = logits + (size_t)SS * BB * VV;

    const int GEMM_SMEM = 2 * 27648;   // 55296 B (2 stages x 6912 words)
    const int DEC_SMEM = 2 * 55296;    // 110592 B (2 stages x 13824 words)
    cudaFuncSetAttribute(k_gemm, cudaFuncAttributeMaxDynamicSharedMemorySize, GEMM_SMEM);
    cudaFuncSetAttribute(k_dec, cudaFuncAttributeMaxDynamicSharedMemorySize, DEC_SMEM);

    unsigned *wq, *wi, *wf, *wd;
    cudaGetSymbolAddress((void**)&wq, g_wq);
    cudaGetSymbolAddress((void**)&wi, g_wi);
    cudaGetSymbolAddress((void**)&wf, g_wf);
    cudaGetSymbolAddress((void**)&wd, g_wd);

    // one-time conversions (inside the graph; amortized over 128 reuses)
    k_cvt_w<<<2048, 256>>>(q_w, wq, 1024, 2048, 0);
    k_cvt_w<<<4096, 256>>>(int_w, wi, 4096, 4096, 1);
    k_cvt_w<<<4096, 256>>>(fin_w, wf, 3072, 4096, 0);
    k_cvt_w<<<8192, 256>>>(dec_w, wd, 32000, 1024, 0);
    k_embed<<<SS * BB, 256>>>(obs, enc_w);
    k_init<<<BB, 256>>>(hidden_init, kinit, vinit, states_full);

    uint4 *bq, *bi, *bf;
    cudaGetSymbolAddress((void**)&bq, g_wq);
    cudaGetSymbolAddress((void**)&bi, g_wi);
    cudaGetSymbolAddress((void**)&bf, g_wf);

    for (int s = 0; s < SS; s++) {
        // q = relu(ln([e,hidden] @ q_w.T + q_b)) -- LN fused into attention kernel
        k_gemm<<<dim3(16, KSPLIT), 256, GEMM_SMEM>>>(0, s, bq, 32, 4, 1024);
        k_lnq_attn<<<BB, 512>>>(q_b, qn_g, qn_b, s);
        // inter = relu(ln([e,q,attn,hidden] @ int_w.T + int_b)); x order [e,hidden,q,attn]
        k_gemm<<<dim3(64, KSPLIT), 256, GEMM_SMEM>>>(0, s, bi, 64, 8, 4096);
        k_ln_int<<<BB, 256>>>(int_b, intn_g, intn_b);
        // final = relu(ln(inter @ fin_w.T + fin_b)) -> split k,v,h
        k_gemm<<<dim3(48, KSPLIT), 256, GEMM_SMEM>>>(1, s, bf, 64, 8, 3072);
        k_ln_fin<<<BB, 256>>>(fin_b, fn_g, fn_b, s, states_full);
    }

    // logits = states @ dec_w.T + dec_b
    k_dec<<<dim3(32, VV / 64), 256, DEC_SMEM>>>(dec_b, logits);
}